// round 4
// baseline (speedup 1.0000x reference)
#include <cuda_runtime.h>
#include <math.h>

// Problem constants
#define H 128
#define P 512
#define B 32
#define K4H 512          // 4*H
#define KBIG 65536       // P*H
#define NCHUNK 37        // split-K chunks: 4 j-tiles * 37 = 148 blocks = 1 full wave
#define NSTEPS 2048      // KBIG / 32

// ---------------- scratch (device globals; no allocation allowed) ----------------
// NOTE: these are referenced ONLY inside device code. Never passed as kernel
// arguments from host (host-side use of a __device__ symbol yields the host
// shadow address -> UVM faults + garbage data).
__device__ float g_fb[B * H];                       // (B,H)
__device__ float g_scores[B * P];                   // (B,P)
__device__ float g_beta[B * P];                     // (B,P)
__device__ float g_gpart[NCHUNK * K4H * B];         // split-K partials (2.42 MB)
__device__ float g_gates[K4H * B];                  // gates [j][b], pre-seeded with bias + Whh part

// Branch-free fast transcendentals (MUFU-based, no libm slow path, no stack)
__device__ __forceinline__ float fsigmoid(float x) {
    return 1.0f / (1.0f + __expf(-x));          // x<<0: __expf->inf -> 0; x>>0: ->1
}
__device__ __forceinline__ float ftanh(float x) {
    float ax = fabsf(x);
    float e  = __expf(2.0f * ax);               // may be +inf
    float t  = 1.0f - 2.0f / (e + 1.0f);        // inf -> 1
    return copysignf(t, x);
}

// ---------------- Kernel 1: warp-per-output small GEMMs ----------------
// Tasks 0..4095:        fb[b][h]     = dot(hak[b], Wf[h])  + bf[h]
// Tasks 4096..20479:    gates0[j][b] = dot(hak[b], Whh[j]) + bih[j] + bhh[j]
__global__ __launch_bounds__(256, 1) void k_small(
    const float* __restrict__ hak, const float* __restrict__ Wf,
    const float* __restrict__ bf,  const float* __restrict__ Whh,
    const float* __restrict__ bih, const float* __restrict__ bhh) {
    int w = blockIdx.x * 8 + (threadIdx.x >> 5);   // global warp id, 0..20479
    int l = threadIdx.x & 31;
    const float* arow;
    const float* wrow;
    if (w < 4096) {
        int b = w >> 7, h = w & 127;
        arow = hak + b * H;
        wrow = Wf + h * H;
    } else {
        int idx = w - 4096;
        int j = idx >> 5, b = idx & 31;
        arow = hak + b * H;
        wrow = Whh + j * H;
    }
    float4 a = *(const float4*)(arow + l * 4);
    float4 v = *(const float4*)(wrow + l * 4);
    float s = a.x * v.x + a.y * v.y + a.z * v.z + a.w * v.w;
#pragma unroll
    for (int o = 16; o > 0; o >>= 1) s += __shfl_xor_sync(0xffffffffu, s, o);
    if (l == 0) {
        if (w < 4096) {
            int b = w >> 7, h = w & 127;
            g_fb[b * H + h] = s + bf[h];
        } else {
            int idx = w - 4096;
            int j = idx >> 5, b = idx & 31;
            g_gates[j * B + b] = s + bih[j] + bhh[j];
        }
    }
}

// ---------------- Kernel 2: scores[b][p] = beta_w . tanh(W_fn @ H_r[p,b] + fb[b]) ----------------
__global__ __launch_bounds__(256, 1) void k_scores(const float* __restrict__ Hr,
                                                   const float* __restrict__ Wfn,
                                                   const float* __restrict__ bw) {
    __shared__ float Wt[128][33];   // [h'][k-in-step]
    __shared__ float Vs[32][33];    // [k][b]
    __shared__ float fbs[B * H];
    __shared__ float bws[H];
    __shared__ float red[32][33];   // [b][ht]

    int p = blockIdx.x;
    int tid = threadIdx.x;
    int ht = tid & 31;       // h' = ht + 32*i  (== lane)
    int bt = tid >> 5;       // b  = bt*4 + j   (== warp)

    for (int i = tid; i < B * H; i += 256) fbs[i] = g_fb[i];
    if (tid < H) bws[tid] = bw[tid];

    float acc[4][4];
#pragma unroll
    for (int i = 0; i < 4; ++i)
#pragma unroll
        for (int j = 0; j < 4; ++j) acc[i][j] = 0.0f;

    for (int s = 0; s < 4; ++s) {
        int ks = s * 32;
        __syncthreads();
#pragma unroll
        for (int r = 0; r < 4; ++r) {
            int q = tid + 256 * r;
            int row = q >> 3;
            int c4 = q & 7;
            float4 v = *(const float4*)&Wfn[row * H + ks + c4 * 4];
            Wt[row][c4 * 4 + 0] = v.x; Wt[row][c4 * 4 + 1] = v.y;
            Wt[row][c4 * 4 + 2] = v.z; Wt[row][c4 * 4 + 3] = v.w;
        }
        {
            int b = tid & 31;
            int c4 = tid >> 5;
            float4 v = *(const float4*)&Hr[p * (B * H) + b * H + ks + c4 * 4];
            Vs[c4 * 4 + 0][b] = v.x; Vs[c4 * 4 + 1][b] = v.y;
            Vs[c4 * 4 + 2][b] = v.z; Vs[c4 * 4 + 3][b] = v.w;
        }
        __syncthreads();
#pragma unroll
        for (int k = 0; k < 32; ++k) {
            float w0 = Wt[ht][k], w1 = Wt[ht + 32][k], w2 = Wt[ht + 64][k], w3 = Wt[ht + 96][k];
            float x0 = Vs[k][bt * 4 + 0], x1 = Vs[k][bt * 4 + 1];
            float x2 = Vs[k][bt * 4 + 2], x3 = Vs[k][bt * 4 + 3];
            acc[0][0] += w0 * x0; acc[0][1] += w0 * x1; acc[0][2] += w0 * x2; acc[0][3] += w0 * x3;
            acc[1][0] += w1 * x0; acc[1][1] += w1 * x1; acc[1][2] += w1 * x2; acc[1][3] += w1 * x3;
            acc[2][0] += w2 * x0; acc[2][1] += w2 * x1; acc[2][2] += w2 * x2; acc[2][3] += w2 * x3;
            acc[3][0] += w3 * x0; acc[3][1] += w3 * x1; acc[3][2] += w3 * x2; acc[3][3] += w3 * x3;
        }
    }
#pragma unroll
    for (int j = 0; j < 4; ++j) {
        int b = bt * 4 + j;
        float ssum = 0.0f;
#pragma unroll
        for (int i = 0; i < 4; ++i) {
            int h = ht + 32 * i;
            ssum += ftanh(acc[i][j] + fbs[b * H + h]) * bws[h];
        }
        red[b][ht] = ssum;
    }
    __syncthreads();
    if (tid < 32) {
        float ssum = 0.0f;
#pragma unroll
        for (int j = 0; j < 32; ++j) ssum += red[tid][j];
        g_scores[tid * P + p] = ssum;  // beta_b omitted: softmax/log_softmax shift-invariant
    }
}

// ---------------- Kernel 3: softmax over P per b; beta + logp output ----------------
__global__ __launch_bounds__(256, 1) void k_softmax(float* __restrict__ out) {
    __shared__ float sm[256];
    int b = blockIdx.x;
    int tid = threadIdx.x;
    float s0 = g_scores[b * P + tid];
    float s1 = g_scores[b * P + tid + 256];
    sm[tid] = fmaxf(s0, s1);
    __syncthreads();
    for (int o = 128; o > 0; o >>= 1) {
        if (tid < o) sm[tid] = fmaxf(sm[tid], sm[tid + o]);
        __syncthreads();
    }
    float mx = sm[0];
    __syncthreads();
    float e0 = __expf(s0 - mx), e1 = __expf(s1 - mx);
    sm[tid] = e0 + e1;
    __syncthreads();
    for (int o = 128; o > 0; o >>= 1) {
        if (tid < o) sm[tid] += sm[tid + o];
        __syncthreads();
    }
    float Z = sm[0];
    float lz = __logf(Z);
    float inv = 1.0f / Z;
    g_beta[b * P + tid] = e0 * inv;
    g_beta[b * P + tid + 256] = e1 * inv;
    out[2 * B * H + b * P + tid] = s0 - mx - lz;
    out[2 * B * H + b * P + tid + 256] = s1 - mx - lz;
}

// ---------------- Kernel 4: big GEMM, split-K. gates_x[j][b] partials ----------------
// x[b][k] formed on the fly: x[b][p*H+h] = H_r[p][b][h] * g_beta[b][p]
// g_beta is read DIRECTLY from the device global (never passed from host).
__global__ __launch_bounds__(256, 1) void k_gemm(const float* __restrict__ Wih,
                                                 const float* __restrict__ Hr) {
    __shared__ float Ws[128][33];   // [j-in-tile][k-in-step]
    __shared__ float Xs[32][33];    // [k][b]
    int jb = blockIdx.x * 128;
    int cch = blockIdx.y;
    int tid = threadIdx.x;
    int jt = tid & 31;   // lane
    int bt = tid >> 5;   // warp

    int s0 = (cch * NSTEPS) / NCHUNK;
    int s1 = ((cch + 1) * NSTEPS) / NCHUNK;

    float acc[4][4];
#pragma unroll
    for (int i = 0; i < 4; ++i)
#pragma unroll
        for (int j = 0; j < 4; ++j) acc[i][j] = 0.0f;

    for (int s = s0; s < s1; ++s) {
        int ks = s * 32;
        __syncthreads();
#pragma unroll
        for (int r = 0; r < 4; ++r) {
            int q = tid + 256 * r;
            int row = q >> 3;
            int c4 = q & 7;
            float4 v = *(const float4*)&Wih[(size_t)(jb + row) * KBIG + ks + c4 * 4];
            Ws[row][c4 * 4 + 0] = v.x; Ws[row][c4 * 4 + 1] = v.y;
            Ws[row][c4 * 4 + 2] = v.z; Ws[row][c4 * 4 + 3] = v.w;
        }
        {
            int b = tid & 31;
            int c4 = tid >> 5;
            int k = ks + c4 * 4;
            int pp = k >> 7;
            int h = k & 127;
            float bv = g_beta[b * P + pp];
            float4 v = *(const float4*)&Hr[pp * (B * H) + b * H + h];
            Xs[c4 * 4 + 0][b] = v.x * bv; Xs[c4 * 4 + 1][b] = v.y * bv;
            Xs[c4 * 4 + 2][b] = v.z * bv; Xs[c4 * 4 + 3][b] = v.w * bv;
        }
        __syncthreads();
#pragma unroll
        for (int k = 0; k < 32; ++k) {
            float w0 = Ws[jt][k], w1 = Ws[jt + 32][k], w2 = Ws[jt + 64][k], w3 = Ws[jt + 96][k];
            float x0 = Xs[k][bt * 4 + 0], x1 = Xs[k][bt * 4 + 1];
            float x2 = Xs[k][bt * 4 + 2], x3 = Xs[k][bt * 4 + 3];
            acc[0][0] += w0 * x0; acc[0][1] += w0 * x1; acc[0][2] += w0 * x2; acc[0][3] += w0 * x3;
            acc[1][0] += w1 * x0; acc[1][1] += w1 * x1; acc[1][2] += w1 * x2; acc[1][3] += w1 * x3;
            acc[2][0] += w2 * x0; acc[2][1] += w2 * x1; acc[2][2] += w2 * x2; acc[2][3] += w2 * x3;
            acc[3][0] += w3 * x0; acc[3][1] += w3 * x1; acc[3][2] += w3 * x2; acc[3][3] += w3 * x3;
        }
    }
#pragma unroll
    for (int i = 0; i < 4; ++i)
#pragma unroll
        for (int j = 0; j < 4; ++j)
            g_gpart[((cch * K4H) + jb + jt + 32 * i) * B + bt * 4 + j] = acc[i][j];
}

// ---------------- Kernel 5: add split-K partials onto pre-seeded gates ----------------
__global__ __launch_bounds__(256, 1) void k_reduce() {
    int t = blockIdx.x * 256 + threadIdx.x;  // 0..16383
    int b = t & 31;
    int j = t >> 5;
    float s = g_gates[j * B + b];            // bias + Whh part (from k_small)
#pragma unroll 1
    for (int c = 0; c < NCHUNK; ++c) s += g_gpart[(c * K4H + j) * B + b];
    g_gates[j * B + b] = s;
}

// ---------------- Kernel 6: LSTM cell + outputs ----------------
__global__ __launch_bounds__(256, 1) void k_lstm(const float* __restrict__ hidden,
                                                 float* __restrict__ out) {
    int t = blockIdx.x * 256 + threadIdx.x;  // 0..4095
    int b = t & 31;      // lane varies b -> gates reads coalesced
    int h = t >> 5;
    float iv = g_gates[(0 * H + h) * B + b];
    float fv = g_gates[(1 * H + h) * B + b];
    float gv = g_gates[(2 * H + h) * B + b];
    float ov = g_gates[(3 * H + h) * B + b];
    float c = fsigmoid(fv) * hidden[b * H + h] + fsigmoid(iv) * ftanh(gv);
    float hn = fsigmoid(ov) * ftanh(c);
    out[b * H + h] = hn;            // h_new (1,B,H)
    out[B * H + b * H + h] = c;     // c_new (1,B,H)
}

// ---------------- launch ----------------
extern "C" void kernel_launch(void* const* d_in, const int* in_sizes, int n_in,
                              void* d_out, int out_size) {
    const float* hak    = (const float*)d_in[0];   // (1,B,H)
    const float* Hr     = (const float*)d_in[1];   // (P,B,H)
    const float* hidden = (const float*)d_in[2];   // (1,B,H)
    const float* Wf     = (const float*)d_in[3];   // (H,H)
    const float* bf     = (const float*)d_in[4];   // (H)
    const float* Wfn    = (const float*)d_in[5];   // (H,H)
    const float* bw     = (const float*)d_in[6];   // (H)
    // d_in[7] = beta_b (scalar): softmax/log_softmax shift-invariant -> unused
    const float* Wih    = (const float*)d_in[8];   // (4H, P*H)
    const float* Whh    = (const float*)d_in[9];   // (4H, H)
    const float* bih    = (const float*)d_in[10];  // (4H)
    const float* bhh    = (const float*)d_in[11];  // (4H)
    float* out = (float*)d_out;

    k_small<<<2560, 256>>>(hak, Wf, bf, Whh, bih, bhh);
    k_scores<<<P, 256>>>(Hr, Wfn, bw);
    k_softmax<<<B, 256>>>(out);
    k_gemm<<<dim3(4, NCHUNK), 256>>>(Wih, Hr);
    k_reduce<<<64, 256>>>();
    k_lstm<<<16, 256>>>(hidden, out);
}

// round 6
// speedup vs baseline: 1.8412x; 1.8412x over previous
#include <cuda_runtime.h>
#include <cstdint>
#include <math.h>

// Problem constants
#define H 128
#define P 512
#define B 32
#define K4H 512          // 4*H
#define KBIG 65536       // P*H
#define NCHUNK 37        // 4 j-tiles * 37 = 148 CTAs = 1 full wave
#define CHUNKS 2048      // KBIG / 32 (k-chunks of 32 floats)
#define STAGES 6

// k_gemm_tc dynamic smem layout. A rows padded to 36 floats (bank-conflict-free
// mma fragment LDS: addr/4 = 36*row + col -> 4*row + col mod 32, all distinct).
#define A_STAGE 18432               // 128 rows * 36 floats * 4B
#define B_STAGE 4608                // 32 rows * 36 floats * 4B
#define OFF_BETA 0                  // 32*16 floats = 2048 B
#define OFF_A    4096
#define OFF_B    (OFF_A + STAGES * A_STAGE)          // 114688
#define GEMM_SMEM (OFF_B + STAGES * B_STAGE)         // 142336

// ---------------- scratch (device globals; device-code use ONLY) ----------------
__device__ float g_fb[B * H];
__device__ float g_scores[B * P];
__device__ float g_beta[B * P];
__device__ float g_gpart[NCHUNK * K4H * B];
__device__ float g_gates[K4H * B];

// ---------------- helpers ----------------
__device__ __forceinline__ float fsigmoid(float x) { return 1.0f / (1.0f + __expf(-x)); }
__device__ __forceinline__ float ftanh(float x) {
    float ax = fabsf(x);
    float e  = __expf(2.0f * ax);
    float t  = 1.0f - 2.0f / (e + 1.0f);
    return copysignf(t, x);
}
__device__ __forceinline__ uint32_t f2tf(float x) {
    uint32_t r;
    asm("cvt.rna.tf32.f32 %0, %1;" : "=r"(r) : "f"(x));
    return r;
}
// D(16x8) += A(16x8,row) * B(8x8,col) ; tf32 inputs, fp32 accum
__device__ __forceinline__ void mma_tf32(float* c, uint32_t a0, uint32_t a1,
                                         uint32_t a2, uint32_t a3,
                                         uint32_t b0, uint32_t b1) {
    asm volatile(
        "mma.sync.aligned.m16n8k8.row.col.f32.tf32.tf32.f32 "
        "{%0,%1,%2,%3}, {%4,%5,%6,%7}, {%8,%9}, {%0,%1,%2,%3};"
        : "+f"(c[0]), "+f"(c[1]), "+f"(c[2]), "+f"(c[3])
        : "r"(a0), "r"(a1), "r"(a2), "r"(a3), "r"(b0), "r"(b1));
}

// ---------------- Kernel 1: warp-per-output small GEMMs ----------------
__global__ __launch_bounds__(256, 1) void k_small(
    const float* __restrict__ hak, const float* __restrict__ Wf,
    const float* __restrict__ bf,  const float* __restrict__ Whh,
    const float* __restrict__ bih, const float* __restrict__ bhh) {
    int w = blockIdx.x * 8 + (threadIdx.x >> 5);
    int l = threadIdx.x & 31;
    const float* arow;
    const float* wrow;
    if (w < 4096) {
        int b = w >> 7, h = w & 127;
        arow = hak + b * H; wrow = Wf + h * H;
    } else {
        int idx = w - 4096;
        int j = idx >> 5, b = idx & 31;
        arow = hak + b * H; wrow = Whh + j * H;
    }
    float4 a = *(const float4*)(arow + l * 4);
    float4 v = *(const float4*)(wrow + l * 4);
    float s = a.x * v.x + a.y * v.y + a.z * v.z + a.w * v.w;
#pragma unroll
    for (int o = 16; o > 0; o >>= 1) s += __shfl_xor_sync(0xffffffffu, s, o);
    if (l == 0) {
        if (w < 4096) {
            int b = w >> 7, h = w & 127;
            g_fb[b * H + h] = s + bf[h];
        } else {
            int idx = w - 4096;
            int j = idx >> 5, b = idx & 31;
            g_gates[j * B + b] = s + bih[j] + bhh[j];
        }
    }
}

// ---------------- Kernel 2: scores ----------------
__global__ __launch_bounds__(256, 1) void k_scores(const float* __restrict__ Hr,
                                                   const float* __restrict__ Wfn,
                                                   const float* __restrict__ bw) {
    __shared__ float Wt[128][33];
    __shared__ float Vs[32][33];
    __shared__ float fbs[B * H];
    __shared__ float bws[H];
    __shared__ float red[32][33];

    int p = blockIdx.x;
    int tid = threadIdx.x;
    int ht = tid & 31;
    int bt = tid >> 5;

    for (int i = tid; i < B * H; i += 256) fbs[i] = g_fb[i];
    if (tid < H) bws[tid] = bw[tid];

    float acc[4][4];
#pragma unroll
    for (int i = 0; i < 4; ++i)
#pragma unroll
        for (int j = 0; j < 4; ++j) acc[i][j] = 0.0f;

    for (int s = 0; s < 4; ++s) {
        int ks = s * 32;
        __syncthreads();
#pragma unroll
        for (int r = 0; r < 4; ++r) {
            int q = tid + 256 * r;
            int row = q >> 3;
            int c4 = q & 7;
            float4 v = *(const float4*)&Wfn[row * H + ks + c4 * 4];
            Wt[row][c4 * 4 + 0] = v.x; Wt[row][c4 * 4 + 1] = v.y;
            Wt[row][c4 * 4 + 2] = v.z; Wt[row][c4 * 4 + 3] = v.w;
        }
        {
            int b = tid & 31;
            int c4 = tid >> 5;
            float4 v = *(const float4*)&Hr[p * (B * H) + b * H + ks + c4 * 4];
            Vs[c4 * 4 + 0][b] = v.x; Vs[c4 * 4 + 1][b] = v.y;
            Vs[c4 * 4 + 2][b] = v.z; Vs[c4 * 4 + 3][b] = v.w;
        }
        __syncthreads();
#pragma unroll
        for (int k = 0; k < 32; ++k) {
            float w0 = Wt[ht][k], w1 = Wt[ht + 32][k], w2 = Wt[ht + 64][k], w3 = Wt[ht + 96][k];
            float x0 = Vs[k][bt * 4 + 0], x1 = Vs[k][bt * 4 + 1];
            float x2 = Vs[k][bt * 4 + 2], x3 = Vs[k][bt * 4 + 3];
            acc[0][0] += w0 * x0; acc[0][1] += w0 * x1; acc[0][2] += w0 * x2; acc[0][3] += w0 * x3;
            acc[1][0] += w1 * x0; acc[1][1] += w1 * x1; acc[1][2] += w1 * x2; acc[1][3] += w1 * x3;
            acc[2][0] += w2 * x0; acc[2][1] += w2 * x1; acc[2][2] += w2 * x2; acc[2][3] += w2 * x3;
            acc[3][0] += w3 * x0; acc[3][1] += w3 * x1; acc[3][2] += w3 * x2; acc[3][3] += w3 * x3;
        }
    }
#pragma unroll
    for (int j = 0; j < 4; ++j) {
        int b = bt * 4 + j;
        float ssum = 0.0f;
#pragma unroll
        for (int i = 0; i < 4; ++i) {
            int h = ht + 32 * i;
            ssum += ftanh(acc[i][j] + fbs[b * H + h]) * bws[h];
        }
        red[b][ht] = ssum;
    }
    __syncthreads();
    if (tid < 32) {
        float ssum = 0.0f;
#pragma unroll
        for (int j = 0; j < 32; ++j) ssum += red[tid][j];
        g_scores[tid * P + p] = ssum;   // beta_b omitted: softmax shift-invariant
    }
}

// ---------------- Kernel 3: softmax + logp ----------------
__global__ __launch_bounds__(256, 1) void k_softmax(float* __restrict__ out) {
    __shared__ float sm[256];
    int b = blockIdx.x;
    int tid = threadIdx.x;
    float s0 = g_scores[b * P + tid];
    float s1 = g_scores[b * P + tid + 256];
    sm[tid] = fmaxf(s0, s1);
    __syncthreads();
    for (int o = 128; o > 0; o >>= 1) {
        if (tid < o) sm[tid] = fmaxf(sm[tid], sm[tid + o]);
        __syncthreads();
    }
    float mx = sm[0];
    __syncthreads();
    float e0 = __expf(s0 - mx), e1 = __expf(s1 - mx);
    sm[tid] = e0 + e1;
    __syncthreads();
    for (int o = 128; o > 0; o >>= 1) {
        if (tid < o) sm[tid] += sm[tid + o];
        __syncthreads();
    }
    float Z = sm[0];
    float lz = __logf(Z);
    float inv = 1.0f / Z;
    g_beta[b * P + tid] = e0 * inv;
    g_beta[b * P + tid + 256] = e1 * inv;
    out[2 * B * H + b * P + tid] = s0 - mx - lz;
    out[2 * B * H + b * P + tid + 256] = s1 - mx - lz;
}

// ---------------- Kernel 4: tf32 mma.sync split-K GEMM, 6-stage cp.async ----------------
// partial[j][b] = sum_k Wih[j][k] * Hr-as-x[b][k] * beta[b][p(k)]
// A = Wih tile (128 x 32 k-chunk), B = raw Hr rows (32 x 32); beta folded into
// B fragments in registers. mma.sync.m16n8k8.tf32 (sm_80+ feature, HMMA on Blackwell).
__global__ __launch_bounds__(256, 1) void k_gemm_tc(const float* __restrict__ Wih,
                                                    const float* __restrict__ Hr) {
    extern __shared__ char smem[];
    int tid = threadIdx.x, wid = tid >> 5, lane = tid & 31;
    int jb = blockIdx.x * 128;
    int cch = blockIdx.y;
    int c0 = (cch * CHUNKS) / NCHUNK, c1 = ((cch + 1) * CHUNKS) / NCHUNK;
    int total = c1 - c0;
    int p0 = c0 >> 2;

    // beta slice: bsl[b*16 + (p - p0)]
    float* bsl = (float*)(smem + OFF_BETA);
    {
        int np = ((c1 - 1) >> 2) - p0 + 1;   // <= 15
        for (int t = tid; t < 32 * 16; t += 256) {
            int b = t >> 4, pi = t & 15;
            if (pi < np) bsl[t] = g_beta[b * P + p0 + pi];
        }
    }

    // cp.async mapping. A tile: 1024 x 16B cells, 4 per thread. B tile: 256 cells, 1 per thread.
    const float* aptr[4];
    uint32_t adst[4];
#pragma unroll
    for (int r = 0; r < 4; ++r) {
        int seg = tid + 256 * r;
        int row = seg >> 3, c16 = seg & 7;
        aptr[r] = Wih + (size_t)(jb + row) * KBIG + c16 * 4;
        adst[r] = row * 144 + c16 * 16;        // 36-float rows
    }
    int bb = tid >> 3;                          // batch row 0..31
    const float* bptr = Hr + bb * H + (tid & 7) * 4;
    uint32_t bdst = bb * 144 + (tid & 7) * 16;
    uint32_t smem_base;
    asm("{ .reg .u64 t; cvta.to.shared.u64 t, %1; cvt.u32.u64 %0, t; }"
        : "=r"(smem_base) : "l"(smem));

    auto issue = [&](int chunk, int st) {
#pragma unroll
        for (int r = 0; r < 4; ++r) {
            uint32_t dst = smem_base + OFF_A + st * A_STAGE + adst[r];
            const void* src = aptr[r] + chunk * 32;
            asm volatile("cp.async.cg.shared.global [%0], [%1], 16;" :: "r"(dst), "l"(src));
        }
        int pp = chunk >> 2, h0 = (chunk & 3) * 32;
        uint32_t dst = smem_base + OFF_B + st * B_STAGE + bdst;
        const void* src = bptr + pp * (B * H) + h0;
        asm volatile("cp.async.cg.shared.global [%0], [%1], 16;" :: "r"(dst), "l"(src));
        asm volatile("cp.async.commit_group;");
    };

    float acc[4][4];
#pragma unroll
    for (int i = 0; i < 4; ++i)
#pragma unroll
        for (int j = 0; j < 4; ++j) acc[i][j] = 0.0f;

    int npro = total < STAGES ? total : STAGES;
    for (int it = 0; it < npro; ++it) issue(c0 + it, it);
    __syncthreads();   // bsl ready (overlapped with prologue issue)

    int r4 = lane >> 2, cc = lane & 3;
    for (int i = 0; i < total; ++i) {
        int st = i % STAGES;
        int rem = total - 1 - i;
        if (rem >= 5)      asm volatile("cp.async.wait_group 5;");
        else if (rem == 4) asm volatile("cp.async.wait_group 4;");
        else if (rem == 3) asm volatile("cp.async.wait_group 3;");
        else if (rem == 2) asm volatile("cp.async.wait_group 2;");
        else if (rem == 1) asm volatile("cp.async.wait_group 1;");
        else               asm volatile("cp.async.wait_group 0;");
        __syncthreads();

        const float* As = (const float*)(smem + OFF_A + st * A_STAGE);
        const float* Bs = (const float*)(smem + OFF_B + st * B_STAGE);
        int pi = ((c0 + i) >> 2) - p0;
        // per-tile beta: B-fragment column n = nt*8 + (lane>>2)
        float bv[4];
#pragma unroll
        for (int nt = 0; nt < 4; ++nt) bv[nt] = bsl[(nt * 8 + r4) * 16 + pi];

#pragma unroll
        for (int ks = 0; ks < 4; ++ks) {
            int k0 = ks * 8;
            uint32_t a0 = f2tf(As[(wid * 16 + r4) * 36 + k0 + cc]);
            uint32_t a1 = f2tf(As[(wid * 16 + r4 + 8) * 36 + k0 + cc]);
            uint32_t a2 = f2tf(As[(wid * 16 + r4) * 36 + k0 + cc + 4]);
            uint32_t a3 = f2tf(As[(wid * 16 + r4 + 8) * 36 + k0 + cc + 4]);
#pragma unroll
            for (int nt = 0; nt < 4; ++nt) {
                uint32_t b0 = f2tf(Bs[(nt * 8 + r4) * 36 + k0 + cc] * bv[nt]);
                uint32_t b1 = f2tf(Bs[(nt * 8 + r4) * 36 + k0 + cc + 4] * bv[nt]);
                mma_tf32(acc[nt], a0, a1, a2, a3, b0, b1);
            }
        }
        __syncthreads();                  // all warps done reading stage st
        if (i + STAGES < total) issue(c0 + i + STAGES, st);
    }

    // epilogue: write split-K partials. c0,c1 = cols 2c,2c+1 (row r); c2,c3 = row+8.
    int c2 = (lane & 3) * 2;
#pragma unroll
    for (int nt = 0; nt < 4; ++nt) {
        int col = nt * 8 + c2;
        int row0 = jb + wid * 16 + r4;
        float2 v01 = make_float2(acc[nt][0], acc[nt][1]);
        float2 v23 = make_float2(acc[nt][2], acc[nt][3]);
        *(float2*)&g_gpart[(cch * K4H + row0) * B + col] = v01;
        *(float2*)&g_gpart[(cch * K4H + row0 + 8) * B + col] = v23;
    }
}

// ---------------- Kernel 5: split-K reduce ----------------
__global__ __launch_bounds__(256, 1) void k_reduce() {
    int t = blockIdx.x * 256 + threadIdx.x;
    int b = t & 31;
    int j = t >> 5;
    float s = g_gates[j * B + b];
#pragma unroll 1
    for (int c = 0; c < NCHUNK; ++c) s += g_gpart[(c * K4H + j) * B + b];
    g_gates[j * B + b] = s;
}

// ---------------- Kernel 6: LSTM cell ----------------
__global__ __launch_bounds__(256, 1) void k_lstm(const float* __restrict__ hidden,
                                                 float* __restrict__ out) {
    int t = blockIdx.x * 256 + threadIdx.x;
    int b = t & 31;
    int h = t >> 5;
    float iv = g_gates[(0 * H + h) * B + b];
    float fv = g_gates[(1 * H + h) * B + b];
    float gv = g_gates[(2 * H + h) * B + b];
    float ov = g_gates[(3 * H + h) * B + b];
    float c = fsigmoid(fv) * hidden[b * H + h] + fsigmoid(iv) * ftanh(gv);
    float hn = fsigmoid(ov) * ftanh(c);
    out[b * H + h] = hn;
    out[B * H + b * H + h] = c;
}

// ---------------- launch ----------------
extern "C" void kernel_launch(void* const* d_in, const int* in_sizes, int n_in,
                              void* d_out, int out_size) {
    const float* hak    = (const float*)d_in[0];
    const float* Hr     = (const float*)d_in[1];
    const float* hidden = (const float*)d_in[2];
    const float* Wf     = (const float*)d_in[3];
    const float* bf     = (const float*)d_in[4];
    const float* Wfn    = (const float*)d_in[5];
    const float* bw     = (const float*)d_in[6];
    // d_in[7] = beta_b (scalar): softmax/log_softmax shift-invariant -> unused
    const float* Wih    = (const float*)d_in[8];
    const float* Whh    = (const float*)d_in[9];
    const float* bih    = (const float*)d_in[10];
    const float* bhh    = (const float*)d_in[11];
    float* out = (float*)d_out;

    static int smem_set = 0;
    if (!smem_set) {
        cudaFuncSetAttribute(k_gemm_tc, cudaFuncAttributeMaxDynamicSharedMemorySize, GEMM_SMEM);
        smem_set = 1;
    }

    k_small<<<2560, 256>>>(hak, Wf, bf, Whh, bih, bhh);
    k_scores<<<P, 256>>>(Hr, Wfn, bw);
    k_softmax<<<B, 256>>>(out);
    k_gemm_tc<<<dim3(4, NCHUNK), 256, GEMM_SMEM>>>(Wih, Hr);
    k_reduce<<<64, 256>>>();
    k_lstm<<<16, 256>>>(hidden, out);
}

// round 7
// speedup vs baseline: 1.9474x; 1.0577x over previous
#include <cuda_runtime.h>
#include <cstdint>
#include <math.h>

// Problem constants
#define H 128
#define P 512
#define B 32
#define K4H 512          // 4*H
#define KBIG 65536       // P*H
#define NCHUNK 74        // 4 j-tiles * 74 = 296 CTAs = 2 CTA/SM, one wave
#define CHUNKS 2048      // KBIG / 32 (k-chunks of 32 floats)
#define STAGES 4

// k_gemm_tc smem layout (rows padded to 36 floats: conflict-free frag LDS)
#define A_STAGE 18432               // 128 rows * 36 floats * 4B
#define B_STAGE 4608                // 32 rows * 36 floats * 4B
#define OFF_BETA 0                  // 32*16 floats = 2048 B
#define OFF_A    4096
#define OFF_B    (OFF_A + STAGES * A_STAGE)          // 77824
#define GEMM_SMEM (OFF_B + STAGES * B_STAGE)         // 96256  (x2 CTA = 192.5KB/SM)

// k_scores_tc smem layout
#define SC_OFF_A   0                                 // 4 chunks * 18432 = 73728
#define SC_OFF_B   73728                             // 4 p * 18432 = 73728
#define SC_OFF_FB  147456                            // fbs_t[128][33] = 16896
#define SC_OFF_RED 164352                            // 8 warps * 32 cols * 4B = 1024
#define SC_SMEM    165376

// ---------------- scratch (device globals; device-code use ONLY) ----------------
__device__ float g_fb[B * H];
__device__ float g_scores[B * P];
__device__ float g_beta[B * P];
__device__ float g_gpart[NCHUNK * K4H * B];          // 4.85 MB
__device__ float g_gates[K4H * B];

// ---------------- helpers ----------------
__device__ __forceinline__ float fsigmoid(float x) { return 1.0f / (1.0f + __expf(-x)); }
__device__ __forceinline__ float ftanh(float x) {
    float ax = fabsf(x);
    float e  = __expf(2.0f * ax);
    float t  = 1.0f - 2.0f / (e + 1.0f);
    return copysignf(t, x);
}
__device__ __forceinline__ uint32_t f2tf(float x) {
    uint32_t r;
    asm("cvt.rna.tf32.f32 %0, %1;" : "=r"(r) : "f"(x));
    return r;
}
__device__ __forceinline__ void mma_tf32(float* c, uint32_t a0, uint32_t a1,
                                         uint32_t a2, uint32_t a3,
                                         uint32_t b0, uint32_t b1) {
    asm volatile(
        "mma.sync.aligned.m16n8k8.row.col.f32.tf32.tf32.f32 "
        "{%0,%1,%2,%3}, {%4,%5,%6,%7}, {%8,%9}, {%0,%1,%2,%3};"
        : "+f"(c[0]), "+f"(c[1]), "+f"(c[2]), "+f"(c[3])
        : "r"(a0), "r"(a1), "r"(a2), "r"(a3), "r"(b0), "r"(b1));
}
__device__ __forceinline__ uint32_t smem_addr(const void* p) {
    uint32_t a;
    asm("{ .reg .u64 t; cvta.to.shared.u64 t, %1; cvt.u32.u64 %0, t; }" : "=r"(a) : "l"(p));
    return a;
}
__device__ __forceinline__ void cpa16(uint32_t dst, const void* src) {
    asm volatile("cp.async.cg.shared.global [%0], [%1], 16;" :: "r"(dst), "l"(src));
}

// ---------------- Kernel 1: warp-per-output small GEMMs ----------------
__global__ __launch_bounds__(256, 1) void k_small(
    const float* __restrict__ hak, const float* __restrict__ Wf,
    const float* __restrict__ bf,  const float* __restrict__ Whh,
    const float* __restrict__ bih, const float* __restrict__ bhh) {
    int w = blockIdx.x * 8 + (threadIdx.x >> 5);
    int l = threadIdx.x & 31;
    const float* arow;
    const float* wrow;
    if (w < 4096) {
        int b = w >> 7, h = w & 127;
        arow = hak + b * H; wrow = Wf + h * H;
    } else {
        int idx = w - 4096;
        int j = idx >> 5, b = idx & 31;
        arow = hak + b * H; wrow = Whh + j * H;
    }
    float4 a = *(const float4*)(arow + l * 4);
    float4 v = *(const float4*)(wrow + l * 4);
    float s = a.x * v.x + a.y * v.y + a.z * v.z + a.w * v.w;
#pragma unroll
    for (int o = 16; o > 0; o >>= 1) s += __shfl_xor_sync(0xffffffffu, s, o);
    if (l == 0) {
        if (w < 4096) {
            int b = w >> 7, h = w & 127;
            g_fb[b * H + h] = s + bf[h];
        } else {
            int idx = w - 4096;
            int j = idx >> 5, b = idx & 31;
            g_gates[j * B + b] = s + bih[j] + bhh[j];
        }
    }
}

// ---------------- Kernel 2: tf32 mma scores ----------------
// Per block: 4 consecutive p. A = Wfn (128x128) loaded once; B = Hr[p] (32x128).
// scores[b][p] = sum_h tanh(fa[h][b] + fb[b][h]) * bw[h]
__global__ __launch_bounds__(256, 1) void k_scores_tc(const float* __restrict__ Hr,
                                                      const float* __restrict__ Wfn,
                                                      const float* __restrict__ bw) {
    extern __shared__ char smem[];
    int tid = threadIdx.x, wid = tid >> 5, lane = tid & 31;
    int p0 = blockIdx.x * 4;
    uint32_t sb = smem_addr(smem);

    // A (Wfn): 4096 16B cells, 16 per thread
#pragma unroll
    for (int r = 0; r < 16; ++r) {
        int idx = tid + 256 * r;
        int chunk = idx >> 10, rem = idx & 1023;
        int row = rem >> 3, c16 = rem & 7;
        cpa16(sb + SC_OFF_A + chunk * 18432 + row * 144 + c16 * 16,
              Wfn + row * H + chunk * 32 + c16 * 4);
    }
    asm volatile("cp.async.commit_group;");
    // B for each of 4 p: 1024 cells, 4 per thread; one group per p
#pragma unroll
    for (int p = 0; p < 4; ++p) {
#pragma unroll
        for (int r = 0; r < 4; ++r) {
            int idx = tid + 256 * r;
            int chunk = idx >> 8, rem = idx & 255;
            int row = rem >> 3, c16 = rem & 7;
            cpa16(sb + SC_OFF_B + p * 18432 + chunk * 4608 + row * 144 + c16 * 16,
                  Hr + (p0 + p) * (B * H) + row * H + chunk * 32 + c16 * 4);
        }
        asm volatile("cp.async.commit_group;");
    }
    // fbs transposed: fbs_t[h*33+b]
    float* fbs_t = (float*)(smem + SC_OFF_FB);
    for (int i = tid; i < B * H; i += 256) {
        int b = i >> 7, h = i & 127;
        fbs_t[h * 33 + b] = g_fb[i];
    }
    float* red = (float*)(smem + SC_OFF_RED);

    int r4 = lane >> 2, cc = lane & 3, c2 = cc * 2;
    int row0 = wid * 16 + r4;
    float bw0 = __ldg(bw + row0), bw1 = __ldg(bw + row0 + 8);

    for (int p = 0; p < 4; ++p) {
        if (p == 0)      asm volatile("cp.async.wait_group 3;");
        else if (p == 1) asm volatile("cp.async.wait_group 2;");
        else if (p == 2) asm volatile("cp.async.wait_group 1;");
        else             asm volatile("cp.async.wait_group 0;");
        __syncthreads();   // S1: tile ready; prev-p red readers done

        float acc[4][4];
#pragma unroll
        for (int i = 0; i < 4; ++i)
#pragma unroll
            for (int j = 0; j < 4; ++j) acc[i][j] = 0.0f;

#pragma unroll
        for (int chunk = 0; chunk < 4; ++chunk) {
            const float* As = (const float*)(smem + SC_OFF_A + chunk * 18432);
            const float* Bs = (const float*)(smem + SC_OFF_B + p * 18432 + chunk * 4608);
#pragma unroll
            for (int ks = 0; ks < 4; ++ks) {
                int k0 = ks * 8;
                uint32_t a0 = f2tf(As[row0 * 36 + k0 + cc]);
                uint32_t a1 = f2tf(As[(row0 + 8) * 36 + k0 + cc]);
                uint32_t a2 = f2tf(As[row0 * 36 + k0 + cc + 4]);
                uint32_t a3 = f2tf(As[(row0 + 8) * 36 + k0 + cc + 4]);
#pragma unroll
                for (int nt = 0; nt < 4; ++nt) {
                    uint32_t b0 = f2tf(Bs[(nt * 8 + r4) * 36 + k0 + cc]);
                    uint32_t b1 = f2tf(Bs[(nt * 8 + r4) * 36 + k0 + cc + 4]);
                    mma_tf32(acc[nt], a0, a1, a2, a3, b0, b1);
                }
            }
        }
        // epilogue: tanh + bw weight, reduce over h
#pragma unroll
        for (int nt = 0; nt < 4; ++nt) {
            int col0 = nt * 8 + c2;
            float cs0 = ftanh(acc[nt][0] + fbs_t[row0 * 33 + col0]) * bw0
                      + ftanh(acc[nt][2] + fbs_t[(row0 + 8) * 33 + col0]) * bw1;
            float cs1 = ftanh(acc[nt][1] + fbs_t[row0 * 33 + col0 + 1]) * bw0
                      + ftanh(acc[nt][3] + fbs_t[(row0 + 8) * 33 + col0 + 1]) * bw1;
#pragma unroll
            for (int o = 4; o < 32; o <<= 1) {
                cs0 += __shfl_xor_sync(0xffffffffu, cs0, o);
                cs1 += __shfl_xor_sync(0xffffffffu, cs1, o);
            }
            if (r4 == 0) {
                red[wid * 32 + col0] = cs0;
                red[wid * 32 + col0 + 1] = cs1;
            }
        }
        __syncthreads();   // S2: red complete
        if (tid < 32) {
            float s = 0.0f;
#pragma unroll
            for (int w = 0; w < 8; ++w) s += red[w * 32 + tid];
            g_scores[tid * P + p0 + p] = s;   // beta_b omitted: softmax shift-invariant
        }
    }
}

// ---------------- Kernel 3: softmax + logp ----------------
__global__ __launch_bounds__(256, 1) void k_softmax(float* __restrict__ out) {
    __shared__ float sm[256];
    int b = blockIdx.x;
    int tid = threadIdx.x;
    float s0 = g_scores[b * P + tid];
    float s1 = g_scores[b * P + tid + 256];
    sm[tid] = fmaxf(s0, s1);
    __syncthreads();
    for (int o = 128; o > 0; o >>= 1) {
        if (tid < o) sm[tid] = fmaxf(sm[tid], sm[tid + o]);
        __syncthreads();
    }
    float mx = sm[0];
    __syncthreads();
    float e0 = __expf(s0 - mx), e1 = __expf(s1 - mx);
    sm[tid] = e0 + e1;
    __syncthreads();
    for (int o = 128; o > 0; o >>= 1) {
        if (tid < o) sm[tid] += sm[tid + o];
        __syncthreads();
    }
    float Z = sm[0];
    float lz = __logf(Z);
    float inv = 1.0f / Z;
    g_beta[b * P + tid] = e0 * inv;
    g_beta[b * P + tid + 256] = e1 * inv;
    out[2 * B * H + b * P + tid] = s0 - mx - lz;
    out[2 * B * H + b * P + tid + 256] = s1 - mx - lz;
}

// ---------------- Kernel 4: tf32 mma split-K GEMM, 4-stage cp.async, 2 CTA/SM ----------------
__global__ __launch_bounds__(256, 2) void k_gemm_tc(const float* __restrict__ Wih,
                                                    const float* __restrict__ Hr) {
    extern __shared__ char smem[];
    int tid = threadIdx.x, wid = tid >> 5, lane = tid & 31;
    int jb = blockIdx.x * 128;
    int cch = blockIdx.y;
    int c0 = (cch * CHUNKS) / NCHUNK, c1 = ((cch + 1) * CHUNKS) / NCHUNK;
    int total = c1 - c0;   // 27 or 28
    int p0 = c0 >> 2;

    float* bsl = (float*)(smem + OFF_BETA);   // bsl[b*16 + (p-p0)]
    {
        int np = ((c1 - 1) >> 2) - p0 + 1;    // <= 8
        for (int t = tid; t < 32 * 16; t += 256) {
            int b = t >> 4, pi = t & 15;
            if (pi < np) bsl[t] = g_beta[b * P + p0 + pi];
        }
    }

    const float* aptr[4];
    uint32_t adst[4];
#pragma unroll
    for (int r = 0; r < 4; ++r) {
        int seg = tid + 256 * r;
        int row = seg >> 3, c16 = seg & 7;
        aptr[r] = Wih + (size_t)(jb + row) * KBIG + c16 * 4;
        adst[r] = row * 144 + c16 * 16;
    }
    int bb = tid >> 3;
    const float* bptr = Hr + bb * H + (tid & 7) * 4;
    uint32_t bdst = bb * 144 + (tid & 7) * 16;
    uint32_t sb = smem_addr(smem);

    auto issue = [&](int chunk, int st) {
#pragma unroll
        for (int r = 0; r < 4; ++r)
            cpa16(sb + OFF_A + st * A_STAGE + adst[r], aptr[r] + chunk * 32);
        int pp = chunk >> 2, h0 = (chunk & 3) * 32;
        cpa16(sb + OFF_B + st * B_STAGE + bdst, bptr + pp * (B * H) + h0);
        asm volatile("cp.async.commit_group;");
    };

    float acc[4][4];
#pragma unroll
    for (int i = 0; i < 4; ++i)
#pragma unroll
        for (int j = 0; j < 4; ++j) acc[i][j] = 0.0f;

    for (int it = 0; it < STAGES; ++it) issue(c0 + it, it);
    __syncthreads();   // bsl ready

    int r4 = lane >> 2, cc = lane & 3;
    for (int i = 0; i < total; ++i) {
        int st = i & 3;
        int rem = total - 1 - i;
        if (rem >= 3)      asm volatile("cp.async.wait_group 3;");
        else if (rem == 2) asm volatile("cp.async.wait_group 2;");
        else if (rem == 1) asm volatile("cp.async.wait_group 1;");
        else               asm volatile("cp.async.wait_group 0;");
        __syncthreads();

        const float* As = (const float*)(smem + OFF_A + st * A_STAGE);
        const float* Bs = (const float*)(smem + OFF_B + st * B_STAGE);
        int pi = ((c0 + i) >> 2) - p0;
        float bv[4];
#pragma unroll
        for (int nt = 0; nt < 4; ++nt) bv[nt] = bsl[(nt * 8 + r4) * 16 + pi];

#pragma unroll
        for (int ks = 0; ks < 4; ++ks) {
            int k0 = ks * 8;
            uint32_t a0 = f2tf(As[(wid * 16 + r4) * 36 + k0 + cc]);
            uint32_t a1 = f2tf(As[(wid * 16 + r4 + 8) * 36 + k0 + cc]);
            uint32_t a2 = f2tf(As[(wid * 16 + r4) * 36 + k0 + cc + 4]);
            uint32_t a3 = f2tf(As[(wid * 16 + r4 + 8) * 36 + k0 + cc + 4]);
#pragma unroll
            for (int nt = 0; nt < 4; ++nt) {
                uint32_t b0 = f2tf(Bs[(nt * 8 + r4) * 36 + k0 + cc] * bv[nt]);
                uint32_t b1 = f2tf(Bs[(nt * 8 + r4) * 36 + k0 + cc + 4] * bv[nt]);
                mma_tf32(acc[nt], a0, a1, a2, a3, b0, b1);
            }
        }
        __syncthreads();
        if (i + STAGES < total) issue(c0 + i + STAGES, st);
    }

    int c2 = (lane & 3) * 2;
#pragma unroll
    for (int nt = 0; nt < 4; ++nt) {
        int col = nt * 8 + c2;
        int row0 = jb + wid * 16 + r4;
        *(float2*)&g_gpart[(cch * K4H + row0) * B + col] = make_float2(acc[nt][0], acc[nt][1]);
        *(float2*)&g_gpart[(cch * K4H + row0 + 8) * B + col] = make_float2(acc[nt][2], acc[nt][3]);
    }
}

// ---------------- Kernel 5: fused split-K reduce + LSTM cell ----------------
__global__ __launch_bounds__(256, 1) void k_fin(const float* __restrict__ hidden,
                                                float* __restrict__ out) {
    int t = blockIdx.x * 256 + threadIdx.x;   // 0..4095
    int b = t & 31;
    int h = (t >> 5) & 127;
    float s[4];
#pragma unroll
    for (int gi = 0; gi < 4; ++gi) s[gi] = g_gates[(gi * H + h) * B + b];
#pragma unroll 1
    for (int c = 0; c < NCHUNK; ++c) {
#pragma unroll
        for (int gi = 0; gi < 4; ++gi)
            s[gi] += g_gpart[(c * K4H + gi * H + h) * B + b];
    }
    float cv = fsigmoid(s[1]) * hidden[b * H + h] + fsigmoid(s[0]) * ftanh(s[2]);
    float hn = fsigmoid(s[3]) * ftanh(cv);
    out[b * H + h] = hn;
    out[B * H + b * H + h] = cv;
}

// ---------------- launch ----------------
extern "C" void kernel_launch(void* const* d_in, const int* in_sizes, int n_in,
                              void* d_out, int out_size) {
    const float* hak    = (const float*)d_in[0];
    const float* Hr     = (const float*)d_in[1];
    const float* hidden = (const float*)d_in[2];
    const float* Wf     = (const float*)d_in[3];
    const float* bf     = (const float*)d_in[4];
    const float* Wfn    = (const float*)d_in[5];
    const float* bw     = (const float*)d_in[6];
    // d_in[7] = beta_b (scalar): softmax/log_softmax shift-invariant -> unused
    const float* Wih    = (const float*)d_in[8];
    const float* Whh    = (const float*)d_in[9];
    const float* bih    = (const float*)d_in[10];
    const float* bhh    = (const float*)d_in[11];
    float* out = (float*)d_out;

    static int smem_set = 0;
    if (!smem_set) {
        cudaFuncSetAttribute(k_gemm_tc, cudaFuncAttributeMaxDynamicSharedMemorySize, GEMM_SMEM);
        cudaFuncSetAttribute(k_scores_tc, cudaFuncAttributeMaxDynamicSharedMemorySize, SC_SMEM);
        smem_set = 1;
    }

    k_small<<<2560, 256>>>(hak, Wf, bf, Whh, bih, bhh);
    k_scores_tc<<<P / 4, 256, SC_SMEM>>>(Hr, Wfn, bw);
    k_softmax<<<B, 256>>>(out);
    k_gemm_tc<<<dim3(4, NCHUNK), 256, GEMM_SMEM>>>(Wih, Hr);
    k_fin<<<16, 256>>>(hidden, out);
}

// round 8
// speedup vs baseline: 2.4329x; 1.2493x over previous
#include <cuda_runtime.h>
#include <cstdint>
#include <math.h>

// Problem constants
#define H 128
#define P 512
#define B 32
#define K4H 512          // 4*H
#define KBIG 65536       // P*H
#define NCHUNK 111       // 4 j-tiles * 111 = 444 CTAs = 3 CTA/SM, one wave
#define CHUNKS 2048      // KBIG / 32 (k-chunks of 32 floats)
#define STAGES 3

// k_gemm_tc smem layout (rows padded to 36 floats: conflict-free frag LDS)
#define A_STAGE 18432               // 128 rows * 36 floats * 4B
#define B_STAGE 4608                // 32 rows * 36 floats * 4B
#define OFF_BETA 0                  // 32*17 floats = 2176 B
#define OFF_A    4096
#define OFF_B    (OFF_A + STAGES * A_STAGE)          // 59392
#define GEMM_SMEM (OFF_B + STAGES * B_STAGE)         // 73216 (x3 CTA = 219.6KB/SM)

// k_scores_tc smem layout
#define SC_OFF_A   0                                 // 4 chunks * 18432 = 73728
#define SC_OFF_B   73728                             // 4 p * 18432 = 73728
#define SC_OFF_FB  147456                            // fbs_t[128][33] = 16896
#define SC_OFF_RED 164352                            // 4 p * 8 warps * 32 * 4B = 4096
#define SC_SMEM    168448

// ---------------- scratch (device globals; device-code use ONLY) ----------------
__device__ float g_fb[B * H];
__device__ float g_scores[B * P];
__device__ float g_beta[B * P];
__device__ float g_gpart[NCHUNK * K4H * B];          // 7.27 MB
__device__ float g_gates[K4H * B];

// ---------------- helpers ----------------
__device__ __forceinline__ float fsigmoid(float x) { return 1.0f / (1.0f + __expf(-x)); }
__device__ __forceinline__ float ftanh(float x) {
    float ax = fabsf(x);
    float e  = __expf(2.0f * ax);
    float t  = 1.0f - 2.0f / (e + 1.0f);
    return copysignf(t, x);
}
__device__ __forceinline__ uint32_t f2tf(float x) {
    uint32_t r;
    asm("cvt.rna.tf32.f32 %0, %1;" : "=r"(r) : "f"(x));
    return r;
}
__device__ __forceinline__ void mma_tf32(float* c, uint32_t a0, uint32_t a1,
                                         uint32_t a2, uint32_t a3,
                                         uint32_t b0, uint32_t b1) {
    asm volatile(
        "mma.sync.aligned.m16n8k8.row.col.f32.tf32.tf32.f32 "
        "{%0,%1,%2,%3}, {%4,%5,%6,%7}, {%8,%9}, {%0,%1,%2,%3};"
        : "+f"(c[0]), "+f"(c[1]), "+f"(c[2]), "+f"(c[3])
        : "r"(a0), "r"(a1), "r"(a2), "r"(a3), "r"(b0), "r"(b1));
}
__device__ __forceinline__ uint32_t smem_addr(const void* p) {
    uint32_t a;
    asm("{ .reg .u64 t; cvta.to.shared.u64 t, %1; cvt.u32.u64 %0, t; }" : "=r"(a) : "l"(p));
    return a;
}
__device__ __forceinline__ void cpa16(uint32_t dst, const void* src) {
    asm volatile("cp.async.cg.shared.global [%0], [%1], 16;" :: "r"(dst), "l"(src));
}

// ---------------- Kernel 1: small GEMMs, 8 outputs per warp ----------------
// Tasks 0..4095:        fb[b][h]     = dot(hak[b], Wf[h])  + bf[h]
// Tasks 4096..20479:    gates0[j][b] = dot(hak[b], Whh[j]) + bih[j] + bhh[j]
__global__ __launch_bounds__(256, 1) void k_small(
    const float* __restrict__ hak, const float* __restrict__ Wf,
    const float* __restrict__ bf,  const float* __restrict__ Whh,
    const float* __restrict__ bih, const float* __restrict__ bhh) {
    int g = blockIdx.x * 8 + (threadIdx.x >> 5);   // warp id, 0..2559
    int l = threadIdx.x & 31;
#pragma unroll
    for (int q = 0; q < 8; ++q) {
        int t = g * 8 + q;
        const float* arow;
        const float* wrow;
        if (t < 4096) {
            int b = t >> 7, h = t & 127;
            arow = hak + b * H; wrow = Wf + h * H;
        } else {
            int idx = t - 4096;
            int j = idx >> 5, b = idx & 31;
            arow = hak + b * H; wrow = Whh + j * H;
        }
        float4 a = *(const float4*)(arow + l * 4);
        float4 v = *(const float4*)(wrow + l * 4);
        float s = a.x * v.x + a.y * v.y + a.z * v.z + a.w * v.w;
#pragma unroll
        for (int o = 16; o > 0; o >>= 1) s += __shfl_xor_sync(0xffffffffu, s, o);
        if (l == 0) {
            if (t < 4096) {
                int b = t >> 7, h = t & 127;
                g_fb[b * H + h] = s + bf[h];
            } else {
                int idx = t - 4096;
                int j = idx >> 5, b = idx & 31;
                g_gates[j * B + b] = s + bih[j] + bhh[j];
            }
        }
    }
}

// ---------------- Kernel 2: tf32 mma scores (4 p per block, deferred reduce) ----------------
__global__ __launch_bounds__(256, 1) void k_scores_tc(const float* __restrict__ Hr,
                                                      const float* __restrict__ Wfn,
                                                      const float* __restrict__ bw) {
    extern __shared__ char smem[];
    int tid = threadIdx.x, wid = tid >> 5, lane = tid & 31;
    int p0 = blockIdx.x * 4;
    uint32_t sb = smem_addr(smem);

    // A (Wfn): 4096 16B cells
#pragma unroll
    for (int r = 0; r < 16; ++r) {
        int idx = tid + 256 * r;
        int chunk = idx >> 10, rem = idx & 1023;
        int row = rem >> 3, c16 = rem & 7;
        cpa16(sb + SC_OFF_A + chunk * 18432 + row * 144 + c16 * 16,
              Wfn + row * H + chunk * 32 + c16 * 4);
    }
    asm volatile("cp.async.commit_group;");
    // B tiles, one group per p
#pragma unroll
    for (int p = 0; p < 4; ++p) {
#pragma unroll
        for (int r = 0; r < 4; ++r) {
            int idx = tid + 256 * r;
            int chunk = idx >> 8, rem = idx & 255;
            int row = rem >> 3, c16 = rem & 7;
            cpa16(sb + SC_OFF_B + p * 18432 + chunk * 4608 + row * 144 + c16 * 16,
                  Hr + (p0 + p) * (B * H) + row * H + chunk * 32 + c16 * 4);
        }
        asm volatile("cp.async.commit_group;");
    }
    float* fbs_t = (float*)(smem + SC_OFF_FB);
    for (int i = tid; i < B * H; i += 256) {
        int b = i >> 7, h = i & 127;
        fbs_t[h * 33 + b] = g_fb[i];
    }
    float* red = (float*)(smem + SC_OFF_RED);

    int r4 = lane >> 2, cc = lane & 3, c2 = cc * 2;
    int row0 = wid * 16 + r4;
    float bw0 = __ldg(bw + row0), bw1 = __ldg(bw + row0 + 8);

#pragma unroll
    for (int p = 0; p < 4; ++p) {
        if (p == 0)      asm volatile("cp.async.wait_group 3;");
        else if (p == 1) asm volatile("cp.async.wait_group 2;");
        else if (p == 2) asm volatile("cp.async.wait_group 1;");
        else             asm volatile("cp.async.wait_group 0;");
        __syncthreads();   // all threads' copies for this p landed (also fbs_t on p=0)

        float acc[4][4];
#pragma unroll
        for (int i = 0; i < 4; ++i)
#pragma unroll
            for (int j = 0; j < 4; ++j) acc[i][j] = 0.0f;

#pragma unroll
        for (int chunk = 0; chunk < 4; ++chunk) {
            const float* As = (const float*)(smem + SC_OFF_A + chunk * 18432);
            const float* Bs = (const float*)(smem + SC_OFF_B + p * 18432 + chunk * 4608);
#pragma unroll
            for (int ks = 0; ks < 4; ++ks) {
                int k0 = ks * 8;
                uint32_t a0 = f2tf(As[row0 * 36 + k0 + cc]);
                uint32_t a1 = f2tf(As[(row0 + 8) * 36 + k0 + cc]);
                uint32_t a2 = f2tf(As[row0 * 36 + k0 + cc + 4]);
                uint32_t a3 = f2tf(As[(row0 + 8) * 36 + k0 + cc + 4]);
#pragma unroll
                for (int nt = 0; nt < 4; ++nt) {
                    uint32_t b0 = f2tf(Bs[(nt * 8 + r4) * 36 + k0 + cc]);
                    uint32_t b1 = f2tf(Bs[(nt * 8 + r4) * 36 + k0 + cc + 4]);
                    mma_tf32(acc[nt], a0, a1, a2, a3, b0, b1);
                }
            }
        }
        // epilogue: tanh + bw weight; per-warp partial into per-p red (no sync here)
#pragma unroll
        for (int nt = 0; nt < 4; ++nt) {
            int col0 = nt * 8 + c2;
            float cs0 = ftanh(acc[nt][0] + fbs_t[row0 * 33 + col0]) * bw0
                      + ftanh(acc[nt][2] + fbs_t[(row0 + 8) * 33 + col0]) * bw1;
            float cs1 = ftanh(acc[nt][1] + fbs_t[row0 * 33 + col0 + 1]) * bw0
                      + ftanh(acc[nt][3] + fbs_t[(row0 + 8) * 33 + col0 + 1]) * bw1;
#pragma unroll
            for (int o = 4; o < 32; o <<= 1) {
                cs0 += __shfl_xor_sync(0xffffffffu, cs0, o);
                cs1 += __shfl_xor_sync(0xffffffffu, cs1, o);
            }
            if (r4 == 0) {
                red[p * 256 + wid * 32 + col0] = cs0;
                red[p * 256 + wid * 32 + col0 + 1] = cs1;
            }
        }
    }
    __syncthreads();
    if (tid < 128) {
        int p = tid >> 5, bb = tid & 31;
        float s = 0.0f;
#pragma unroll
        for (int w = 0; w < 8; ++w) s += red[p * 256 + w * 32 + bb];
        g_scores[bb * P + p0 + p] = s;   // beta_b omitted: softmax shift-invariant
    }
}

// ---------------- Kernel 3: softmax + logp ----------------
__global__ __launch_bounds__(256, 1) void k_softmax(float* __restrict__ out) {
    __shared__ float sm[256];
    int b = blockIdx.x;
    int tid = threadIdx.x;
    float s0 = g_scores[b * P + tid];
    float s1 = g_scores[b * P + tid + 256];
    sm[tid] = fmaxf(s0, s1);
    __syncthreads();
    for (int o = 128; o > 0; o >>= 1) {
        if (tid < o) sm[tid] = fmaxf(sm[tid], sm[tid + o]);
        __syncthreads();
    }
    float mx = sm[0];
    __syncthreads();
    float e0 = __expf(s0 - mx), e1 = __expf(s1 - mx);
    sm[tid] = e0 + e1;
    __syncthreads();
    for (int o = 128; o > 0; o >>= 1) {
        if (tid < o) sm[tid] += sm[tid + o];
        __syncthreads();
    }
    float Z = sm[0];
    float lz = __logf(Z);
    float inv = 1.0f / Z;
    g_beta[b * P + tid] = e0 * inv;
    g_beta[b * P + tid + 256] = e1 * inv;
    out[2 * B * H + b * P + tid] = s0 - mx - lz;
    out[2 * B * H + b * P + tid + 256] = s1 - mx - lz;
}

// ---------------- Kernel 4: tf32 mma split-K GEMM, 3 CTA/SM, 1 barrier/iter ----------------
__global__ __launch_bounds__(256, 3) void k_gemm_tc(const float* __restrict__ Wih,
                                                    const float* __restrict__ Hr) {
    extern __shared__ char smem[];
    int tid = threadIdx.x, wid = tid >> 5, lane = tid & 31;
    int jb = blockIdx.x * 128;
    int cch = blockIdx.y;
    int c0 = (cch * CHUNKS) / NCHUNK, c1 = ((cch + 1) * CHUNKS) / NCHUNK;
    int total = c1 - c0;   // 18 or 19
    int p0 = c0 >> 2;

    const float* aptr[4];
    uint32_t adst[4];
#pragma unroll
    for (int r = 0; r < 4; ++r) {
        int seg = tid + 256 * r;
        int row = seg >> 3, c16 = seg & 7;
        aptr[r] = Wih + (size_t)(jb + row) * KBIG + c16 * 4;
        adst[r] = row * 144 + c16 * 16;
    }
    int bb = tid >> 3;
    const float* bptr = Hr + bb * H + (tid & 7) * 4;
    uint32_t bdst = bb * 144 + (tid & 7) * 16;
    uint32_t sb = smem_addr(smem);

    auto issue = [&](int chunk, int st) {
#pragma unroll
        for (int r = 0; r < 4; ++r)
            cpa16(sb + OFF_A + st * A_STAGE + adst[r], aptr[r] + chunk * 32);
        int pp = chunk >> 2, h0 = (chunk & 3) * 32;
        cpa16(sb + OFF_B + st * B_STAGE + bdst, bptr + pp * (B * H) + h0);
        asm volatile("cp.async.commit_group;");
    };

    // prologue: STAGES-1 chunks in flight
    issue(c0 + 0, 0);
    issue(c0 + 1, 1);

    float* bsl = (float*)(smem + OFF_BETA);   // bsl[b*17 + (p-p0)]
    {
        int np = ((c1 - 1) >> 2) - p0 + 1;    // <= 6
        for (int t = tid; t < 32 * 17; t += 256) {
            int b = t / 17, pi = t - b * 17;
            if (pi < np) bsl[t] = g_beta[b * P + p0 + pi];
        }
    }

    float acc[4][4];
#pragma unroll
    for (int i = 0; i < 4; ++i)
#pragma unroll
        for (int j = 0; j < 4; ++j) acc[i][j] = 0.0f;

    int r4 = lane >> 2, cc = lane & 3;
    for (int i = 0; i < total; ++i) {
        int st = i % STAGES;
        if (i == total - 1) asm volatile("cp.async.wait_group 0;");
        else                asm volatile("cp.async.wait_group 1;");
        __syncthreads();   // stage st data landed for ALL threads; stage (i-1)%S free
        if (i + STAGES - 1 < total) issue(c0 + i + STAGES - 1, (i + STAGES - 1) % STAGES);

        const float* As = (const float*)(smem + OFF_A + st * A_STAGE);
        const float* Bs = (const float*)(smem + OFF_B + st * B_STAGE);
        int pi = ((c0 + i) >> 2) - p0;
        float bv[4];
#pragma unroll
        for (int nt = 0; nt < 4; ++nt) bv[nt] = bsl[(nt * 8 + r4) * 17 + pi];

#pragma unroll
        for (int ks = 0; ks < 4; ++ks) {
            int k0 = ks * 8;
            uint32_t a0 = f2tf(As[(wid * 16 + r4) * 36 + k0 + cc]);
            uint32_t a1 = f2tf(As[(wid * 16 + r4 + 8) * 36 + k0 + cc]);
            uint32_t a2 = f2tf(As[(wid * 16 + r4) * 36 + k0 + cc + 4]);
            uint32_t a3 = f2tf(As[(wid * 16 + r4 + 8) * 36 + k0 + cc + 4]);
#pragma unroll
            for (int nt = 0; nt < 4; ++nt) {
                uint32_t b0 = f2tf(Bs[(nt * 8 + r4) * 36 + k0 + cc] * bv[nt]);
                uint32_t b1 = f2tf(Bs[(nt * 8 + r4) * 36 + k0 + cc + 4] * bv[nt]);
                mma_tf32(acc[nt], a0, a1, a2, a3, b0, b1);
            }
        }
    }

    int c2 = (lane & 3) * 2;
#pragma unroll
    for (int nt = 0; nt < 4; ++nt) {
        int col = nt * 8 + c2;
        int row0 = jb + wid * 16 + r4;
        *(float2*)&g_gpart[(cch * K4H + row0) * B + col] = make_float2(acc[nt][0], acc[nt][1]);
        *(float2*)&g_gpart[(cch * K4H + row0 + 8) * B + col] = make_float2(acc[nt][2], acc[nt][3]);
    }
}

// ---------------- Kernel 5: fused split-K reduce + LSTM (1 h-row per block) ----------------
__global__ __launch_bounds__(256, 1) void k_fin(const float* __restrict__ hidden,
                                                float* __restrict__ out) {
    __shared__ float red[8][4][32];
    int b = threadIdx.x & 31;
    int s = threadIdx.x >> 5;            // slice 0..7
    int h = blockIdx.x;                  // 0..127
    float acc[4] = {0.f, 0.f, 0.f, 0.f};
    int cbeg = s * 14;
    int cend = cbeg + 14 < NCHUNK ? cbeg + 14 : NCHUNK;
    for (int c = cbeg; c < cend; ++c) {
#pragma unroll
        for (int gi = 0; gi < 4; ++gi)
            acc[gi] += g_gpart[(c * K4H + gi * H + h) * B + b];
    }
#pragma unroll
    for (int gi = 0; gi < 4; ++gi) red[s][gi][b] = acc[gi];
    __syncthreads();
    if (threadIdx.x < 32) {
        float sg[4];
#pragma unroll
        for (int gi = 0; gi < 4; ++gi) {
            float v = g_gates[(gi * H + h) * B + b];
#pragma unroll
            for (int w = 0; w < 8; ++w) v += red[w][gi][b];
            sg[gi] = v;
        }
        float cv = fsigmoid(sg[1]) * hidden[b * H + h] + fsigmoid(sg[0]) * ftanh(sg[2]);
        float hn = fsigmoid(sg[3]) * ftanh(cv);
        out[b * H + h] = hn;
        out[B * H + b * H + h] = cv;
    }
}

// ---------------- launch ----------------
extern "C" void kernel_launch(void* const* d_in, const int* in_sizes, int n_in,
                              void* d_out, int out_size) {
    const float* hak    = (const float*)d_in[0];
    const float* Hr     = (const float*)d_in[1];
    const float* hidden = (const float*)d_in[2];
    const float* Wf     = (const float*)d_in[3];
    const float* bf     = (const float*)d_in[4];
    const float* Wfn    = (const float*)d_in[5];
    const float* bw     = (const float*)d_in[6];
    // d_in[7] = beta_b (scalar): softmax/log_softmax shift-invariant -> unused
    const float* Wih    = (const float*)d_in[8];
    const float* Whh    = (const float*)d_in[9];
    const float* bih    = (const float*)d_in[10];
    const float* bhh    = (const float*)d_in[11];
    float* out = (float*)d_out;

    static int smem_set = 0;
    if (!smem_set) {
        cudaFuncSetAttribute(k_gemm_tc, cudaFuncAttributeMaxDynamicSharedMemorySize, GEMM_SMEM);
        cudaFuncSetAttribute(k_scores_tc, cudaFuncAttributeMaxDynamicSharedMemorySize, SC_SMEM);
        smem_set = 1;
    }

    k_small<<<320, 256>>>(hak, Wf, bf, Whh, bih, bhh);
    k_scores_tc<<<P / 4, 256, SC_SMEM>>>(Hr, Wfn, bw);
    k_softmax<<<B, 256>>>(out);
    k_gemm_tc<<<dim3(4, NCHUNK), 256, GEMM_SMEM>>>(Wih, Hr);
    k_fin<<<H, 256>>>(hidden, out);
}

// round 9
// speedup vs baseline: 2.4653x; 1.0133x over previous
#include <cuda_runtime.h>
#include <cstdint>
#include <math.h>

// Problem constants
#define H 128
#define P 512
#define B 32
#define K4H 512          // 4*H
#define KBIG 65536       // P*H
#define NCHUNK 111       // 4 j-tiles * 111 = 444 CTAs = 3 CTA/SM, one wave
#define CHUNKS 2048      // KBIG / 32 (k-chunks of 32 floats)
#define STAGES 3

// k_gemm_tc smem layout (A rows padded to 36 floats: conflict-free frag LDS)
#define A_STAGE 18432               // 128 rows * 36 floats * 4B
#define B_STAGE 4608                // 32 rows * 36 floats * 4B
#define OFF_BETA 0                  // 32*17 floats = 2176 B
#define OFF_BC   2304               // 512 uint2 = 4096 B (tf32+beta B tile, frag order)
#define OFF_A    6400
#define OFF_B    (OFF_A + STAGES * A_STAGE)          // 61696
#define GEMM_SMEM (OFF_B + STAGES * B_STAGE)         // 75520 (x3 CTA = 226.6KB/SM)

// k_scores_tc smem layout
#define SC_OFF_A   0                                 // 4 chunks * 18432 = 73728
#define SC_OFF_B   73728                             // 4 p * 18432 = 73728
#define SC_OFF_FB  147456                            // fbs_t[128][33] = 16896
#define SC_OFF_RED 164352                            // 4 p * 8 warps * 32 * 4B = 4096
#define SC_OFF_BC  168448                            // 4 chunks * 512 uint2 = 16384
#define SC_SMEM    184832

// ---------------- scratch (device globals; device-code use ONLY) ----------------
__device__ float g_fb[B * H];
__device__ float g_scores[B * P];
__device__ float g_beta[B * P];
__device__ float g_gpart[NCHUNK * K4H * B];          // 7.27 MB
__device__ float g_gates[K4H * B];

// ---------------- helpers ----------------
__device__ __forceinline__ float fsigmoid(float x) { return 1.0f / (1.0f + __expf(-x)); }
__device__ __forceinline__ float ftanh(float x) {
    float ax = fabsf(x);
    float e  = __expf(2.0f * ax);
    float t  = 1.0f - 2.0f / (e + 1.0f);
    return copysignf(t, x);
}
__device__ __forceinline__ uint32_t f2tf(float x) {
    uint32_t r;
    asm("cvt.rna.tf32.f32 %0, %1;" : "=r"(r) : "f"(x));
    return r;
}
__device__ __forceinline__ void mma_tf32(float* c, uint32_t a0, uint32_t a1,
                                         uint32_t a2, uint32_t a3,
                                         uint32_t b0, uint32_t b1) {
    asm volatile(
        "mma.sync.aligned.m16n8k8.row.col.f32.tf32.tf32.f32 "
        "{%0,%1,%2,%3}, {%4,%5,%6,%7}, {%8,%9}, {%0,%1,%2,%3};"
        : "+f"(c[0]), "+f"(c[1]), "+f"(c[2]), "+f"(c[3])
        : "r"(a0), "r"(a1), "r"(a2), "r"(a3), "r"(b0), "r"(b1));
}
__device__ __forceinline__ uint32_t smem_addr(const void* p) {
    uint32_t a;
    asm("{ .reg .u64 t; cvta.to.shared.u64 t, %1; cvt.u32.u64 %0, t; }" : "=r"(a) : "l"(p));
    return a;
}
__device__ __forceinline__ void cpa16(uint32_t dst, const void* src) {
    asm volatile("cp.async.cg.shared.global [%0], [%1], 16;" :: "r"(dst), "l"(src));
}

// ---------------- Kernel 1: small GEMMs, 8 outputs per warp ----------------
__global__ __launch_bounds__(256, 1) void k_small(
    const float* __restrict__ hak, const float* __restrict__ Wf,
    const float* __restrict__ bf,  const float* __restrict__ Whh,
    const float* __restrict__ bih, const float* __restrict__ bhh) {
    int g = blockIdx.x * 8 + (threadIdx.x >> 5);   // warp id, 0..2559
    int l = threadIdx.x & 31;
#pragma unroll
    for (int q = 0; q < 8; ++q) {
        int t = g * 8 + q;
        const float* arow;
        const float* wrow;
        if (t < 4096) {
            int b = t >> 7, h = t & 127;
            arow = hak + b * H; wrow = Wf + h * H;
        } else {
            int idx = t - 4096;
            int j = idx >> 5, b = idx & 31;
            arow = hak + b * H; wrow = Whh + j * H;
        }
        float4 a = *(const float4*)(arow + l * 4);
        float4 v = *(const float4*)(wrow + l * 4);
        float s = a.x * v.x + a.y * v.y + a.z * v.z + a.w * v.w;
#pragma unroll
        for (int o = 16; o > 0; o >>= 1) s += __shfl_xor_sync(0xffffffffu, s, o);
        if (l == 0) {
            if (t < 4096) {
                int b = t >> 7, h = t & 127;
                g_fb[b * H + h] = s + bf[h];
            } else {
                int idx = t - 4096;
                int j = idx >> 5, b = idx & 31;
                g_gates[j * B + b] = s + bih[j] + bhh[j];
            }
        }
    }
}

// ---------------- Kernel 2: tf32 mma scores, preconverted operands ----------------
__global__ __launch_bounds__(256, 1) void k_scores_tc(const float* __restrict__ Hr,
                                                      const float* __restrict__ Wfn,
                                                      const float* __restrict__ bw) {
    extern __shared__ char smem[];
    int tid = threadIdx.x, wid = tid >> 5, lane = tid & 31;
    int p0 = blockIdx.x * 4;
    uint32_t sb = smem_addr(smem);

    // A (Wfn): 4096 16B cells
#pragma unroll
    for (int r = 0; r < 16; ++r) {
        int idx = tid + 256 * r;
        int chunk = idx >> 10, rem = idx & 1023;
        int row = rem >> 3, c16 = rem & 7;
        cpa16(sb + SC_OFF_A + chunk * 18432 + row * 144 + c16 * 16,
              Wfn + row * H + chunk * 32 + c16 * 4);
    }
    asm volatile("cp.async.commit_group;");
    // B tiles, one group per p
#pragma unroll
    for (int p = 0; p < 4; ++p) {
#pragma unroll
        for (int r = 0; r < 4; ++r) {
            int idx = tid + 256 * r;
            int chunk = idx >> 8, rem = idx & 255;
            int row = rem >> 3, c16 = rem & 7;
            cpa16(sb + SC_OFF_B + p * 18432 + chunk * 4608 + row * 144 + c16 * 16,
                  Hr + (p0 + p) * (B * H) + row * H + chunk * 32 + c16 * 4);
        }
        asm volatile("cp.async.commit_group;");
    }
    float* fbs_t = (float*)(smem + SC_OFF_FB);
    for (int i = tid; i < B * H; i += 256) {
        int b = i >> 7, h = i & 127;
        fbs_t[h * 33 + b] = g_fb[i];
    }
    float* red = (float*)(smem + SC_OFF_RED);
    uint2* BcU = (uint2*)(smem + SC_OFF_BC);

    int r4 = lane >> 2, cc = lane & 3, c2 = cc * 2;
    int row0 = wid * 16 + r4;
    float bw0 = __ldg(bw + row0), bw1 = __ldg(bw + row0 + 8);

#pragma unroll
    for (int p = 0; p < 4; ++p) {
        if (p == 0)      asm volatile("cp.async.wait_group 3;");
        else if (p == 1) asm volatile("cp.async.wait_group 2;");
        else if (p == 2) asm volatile("cp.async.wait_group 1;");
        else             asm volatile("cp.async.wait_group 0;");
        __syncthreads();   // raw tiles landed (p=0: also A + fbs_t)

        if (p == 0) {
            // one-time in-place A conversion to tf32 bits
            float* Af = (float*)(smem + SC_OFF_A);
            uint32_t* Au = (uint32_t*)(smem + SC_OFF_A);
            for (int i = tid; i < 4 * 4608; i += 256) Au[i] = f2tf(Af[i]);
        }
        // preconvert this p's B (4 chunks) into fragment-ordered tf32
        {
            const float* Braw = (const float*)(smem + SC_OFF_B + p * 18432);
#pragma unroll
            for (int q = 0; q < 8; ++q) {
                int f = tid + q * 256;            // 0..2047
                int chunk = f >> 9, fr = f & 511;
                int ks = fr >> 7, rem = fr & 127;
                int nt = rem >> 5, r4p = (rem >> 2) & 7, ccp = fr & 3;
                int n = nt * 8 + r4p;
                const float* src = Braw + chunk * 1152 + n * 36 + ks * 8 + ccp;
                uint2 w;
                w.x = f2tf(src[0]);
                w.y = f2tf(src[4]);
                BcU[f] = w;
            }
        }
        __syncthreads();   // converted A + Bc ready

        float acc[4][4];
#pragma unroll
        for (int i = 0; i < 4; ++i)
#pragma unroll
            for (int j = 0; j < 4; ++j) acc[i][j] = 0.0f;

#pragma unroll
        for (int chunk = 0; chunk < 4; ++chunk) {
            const uint32_t* Au = (const uint32_t*)(smem + SC_OFF_A + chunk * 18432);
            const uint2* Bc = BcU + chunk * 512;
#pragma unroll
            for (int ks = 0; ks < 4; ++ks) {
                int k0 = ks * 8;
                uint32_t a0 = Au[row0 * 36 + k0 + cc];
                uint32_t a1 = Au[(row0 + 8) * 36 + k0 + cc];
                uint32_t a2 = Au[row0 * 36 + k0 + cc + 4];
                uint32_t a3 = Au[(row0 + 8) * 36 + k0 + cc + 4];
#pragma unroll
                for (int nt = 0; nt < 4; ++nt) {
                    uint2 bv2 = Bc[ks * 128 + nt * 32 + (r4 << 2) + cc];
                    mma_tf32(acc[nt], a0, a1, a2, a3, bv2.x, bv2.y);
                }
            }
        }
        // epilogue: tanh + bw weight; per-warp partial into per-p red
#pragma unroll
        for (int nt = 0; nt < 4; ++nt) {
            int col0 = nt * 8 + c2;
            float cs0 = ftanh(acc[nt][0] + fbs_t[row0 * 33 + col0]) * bw0
                      + ftanh(acc[nt][2] + fbs_t[(row0 + 8) * 33 + col0]) * bw1;
            float cs1 = ftanh(acc[nt][1] + fbs_t[row0 * 33 + col0 + 1]) * bw0
                      + ftanh(acc[nt][3] + fbs_t[(row0 + 8) * 33 + col0 + 1]) * bw1;
#pragma unroll
            for (int o = 4; o < 32; o <<= 1) {
                cs0 += __shfl_xor_sync(0xffffffffu, cs0, o);
                cs1 += __shfl_xor_sync(0xffffffffu, cs1, o);
            }
            if (r4 == 0) {
                red[p * 256 + wid * 32 + col0] = cs0;
                red[p * 256 + wid * 32 + col0 + 1] = cs1;
            }
        }
    }
    __syncthreads();
    if (tid < 128) {
        int p = tid >> 5, bb = tid & 31;
        float s = 0.0f;
#pragma unroll
        for (int w = 0; w < 8; ++w) s += red[p * 256 + w * 32 + bb];
        g_scores[bb * P + p0 + p] = s;   // beta_b omitted: softmax shift-invariant
    }
}

// ---------------- Kernel 3: softmax + logp ----------------
__global__ __launch_bounds__(256, 1) void k_softmax(float* __restrict__ out) {
    __shared__ float sm[256];
    int b = blockIdx.x;
    int tid = threadIdx.x;
    float s0 = g_scores[b * P + tid];
    float s1 = g_scores[b * P + tid + 256];
    sm[tid] = fmaxf(s0, s1);
    __syncthreads();
    for (int o = 128; o > 0; o >>= 1) {
        if (tid < o) sm[tid] = fmaxf(sm[tid], sm[tid + o]);
        __syncthreads();
    }
    float mx = sm[0];
    __syncthreads();
    float e0 = __expf(s0 - mx), e1 = __expf(s1 - mx);
    sm[tid] = e0 + e1;
    __syncthreads();
    for (int o = 128; o > 0; o >>= 1) {
        if (tid < o) sm[tid] += sm[tid + o];
        __syncthreads();
    }
    float Z = sm[0];
    float lz = __logf(Z);
    float inv = 1.0f / Z;
    g_beta[b * P + tid] = e0 * inv;
    g_beta[b * P + tid + 256] = e1 * inv;
    out[2 * B * H + b * P + tid] = s0 - mx - lz;
    out[2 * B * H + b * P + tid + 256] = s1 - mx - lz;
}

// ---------------- Kernel 4: tf32 mma split-K GEMM, cooperative B preconvert ----------------
__global__ __launch_bounds__(256, 3) void k_gemm_tc(const float* __restrict__ Wih,
                                                    const float* __restrict__ Hr) {
    extern __shared__ char smem[];
    int tid = threadIdx.x, wid = tid >> 5, lane = tid & 31;
    int jb = blockIdx.x * 128;
    int cch = blockIdx.y;
    int c0 = (cch * CHUNKS) / NCHUNK, c1 = ((cch + 1) * CHUNKS) / NCHUNK;
    int total = c1 - c0;   // 18 or 19
    int p0 = c0 >> 2;

    const float* aptr[4];
    uint32_t adst[4];
#pragma unroll
    for (int r = 0; r < 4; ++r) {
        int seg = tid + 256 * r;
        int row = seg >> 3, c16 = seg & 7;
        aptr[r] = Wih + (size_t)(jb + row) * KBIG + c16 * 4;
        adst[r] = row * 144 + c16 * 16;
    }
    int bb = tid >> 3;
    const float* bptr = Hr + bb * H + (tid & 7) * 4;
    uint32_t bdst = bb * 144 + (tid & 7) * 16;
    uint32_t sb = smem_addr(smem);

    auto issue = [&](int chunk, int st) {
#pragma unroll
        for (int r = 0; r < 4; ++r)
            cpa16(sb + OFF_A + st * A_STAGE + adst[r], aptr[r] + chunk * 32);
        int pp = chunk >> 2, h0 = (chunk & 3) * 32;
        cpa16(sb + OFF_B + st * B_STAGE + bdst, bptr + pp * (B * H) + h0);
        asm volatile("cp.async.commit_group;");
    };

    issue(c0 + 0, 0);
    issue(c0 + 1, 1);

    float* bsl = (float*)(smem + OFF_BETA);   // bsl[b*17 + (p-p0)]
    {
        int np = ((c1 - 1) >> 2) - p0 + 1;    // <= 6
        for (int t = tid; t < 32 * 17; t += 256) {
            int b = t / 17, pi = t - b * 17;
            if (pi < np) bsl[t] = g_beta[b * P + p0 + pi];
        }
    }
    uint2* BcU = (uint2*)(smem + OFF_BC);

    float acc[4][4];
#pragma unroll
    for (int i = 0; i < 4; ++i)
#pragma unroll
        for (int j = 0; j < 4; ++j) acc[i][j] = 0.0f;

    // preconvert-thread decomposition (fixed per thread, two f values)
    int pc_ks[2], pc_n[2], pc_cc[2];
#pragma unroll
    for (int q = 0; q < 2; ++q) {
        int f = tid + q * 256;
        pc_ks[q] = f >> 7;
        int rem = f & 127;
        pc_n[q] = (rem >> 5) * 8 + ((rem >> 2) & 7);
        pc_cc[q] = f & 3;
    }

    int r4 = lane >> 2, cc = lane & 3;
    for (int i = 0; i < total; ++i) {
        int st = i % STAGES;
        if (i == total - 1) asm volatile("cp.async.wait_group 0;");
        else                asm volatile("cp.async.wait_group 1;");
        __syncthreads();   // stage st raw landed; stage (i+2)%S raw free
        if (i + 2 < total) issue(c0 + i + 2, (i + 2) % STAGES);

        // cooperative B preconvert: tf32 + beta, fragment order
        {
            int pi = ((c0 + i) >> 2) - p0;
            const float* Braw = (const float*)(smem + OFF_B + st * B_STAGE);
#pragma unroll
            for (int q = 0; q < 2; ++q) {
                float bv = bsl[pc_n[q] * 17 + pi];
                const float* src = Braw + pc_n[q] * 36 + pc_ks[q] * 8 + pc_cc[q];
                uint2 w;
                w.x = f2tf(src[0] * bv);
                w.y = f2tf(src[4] * bv);
                BcU[tid + q * 256] = w;
            }
        }
        __syncthreads();   // Bc ready

        const float* As = (const float*)(smem + OFF_A + st * A_STAGE);
#pragma unroll
        for (int ks = 0; ks < 4; ++ks) {
            int k0 = ks * 8;
            uint32_t a0 = f2tf(As[(wid * 16 + r4) * 36 + k0 + cc]);
            uint32_t a1 = f2tf(As[(wid * 16 + r4 + 8) * 36 + k0 + cc]);
            uint32_t a2 = f2tf(As[(wid * 16 + r4) * 36 + k0 + cc + 4]);
            uint32_t a3 = f2tf(As[(wid * 16 + r4 + 8) * 36 + k0 + cc + 4]);
#pragma unroll
            for (int nt = 0; nt < 4; ++nt) {
                uint2 bv2 = BcU[ks * 128 + nt * 32 + (r4 << 2) + cc];
                mma_tf32(acc[nt], a0, a1, a2, a3, bv2.x, bv2.y);
            }
        }
    }

    int c2 = (lane & 3) * 2;
#pragma unroll
    for (int nt = 0; nt < 4; ++nt) {
        int col = nt * 8 + c2;
        int row0 = jb + wid * 16 + r4;
        *(float2*)&g_gpart[(cch * K4H + row0) * B + col] = make_float2(acc[nt][0], acc[nt][1]);
        *(float2*)&g_gpart[(cch * K4H + row0 + 8) * B + col] = make_float2(acc[nt][2], acc[nt][3]);
    }
}

// ---------------- Kernel 5: fused split-K reduce + LSTM (1 h-row per block) ----------------
__global__ __launch_bounds__(256, 1) void k_fin(const float* __restrict__ hidden,
                                                float* __restrict__ out) {
    __shared__ float red[8][4][32];
    int b = threadIdx.x & 31;
    int s = threadIdx.x >> 5;            // slice 0..7
    int h = blockIdx.x;                  // 0..127
    float acc[4] = {0.f, 0.f, 0.f, 0.f};
    int cbeg = s * 14;
    int cend = cbeg + 14 < NCHUNK ? cbeg + 14 : NCHUNK;
    for (int c = cbeg; c < cend; ++c) {
#pragma unroll
        for (int gi = 0; gi < 4; ++gi)
            acc[gi] += g_gpart[(c * K4H + gi * H + h) * B + b];
    }
#pragma unroll
    for (int gi = 0; gi < 4; ++gi) red[s][gi][b] = acc[gi];
    __syncthreads();
    if (threadIdx.x < 32) {
        float sg[4];
#pragma unroll
        for (int gi = 0; gi < 4; ++gi) {
            float v = g_gates[(gi * H + h) * B + b];
#pragma unroll
            for (int w = 0; w < 8; ++w) v += red[w][gi][b];
            sg[gi] = v;
        }
        float cv = fsigmoid(sg[1]) * hidden[b * H + h] + fsigmoid(sg[0]) * ftanh(sg[2]);
        float hn = fsigmoid(sg[3]) * ftanh(cv);
        out[b * H + h] = hn;
        out[B * H + b * H + h] = cv;
    }
}

// ---------------- launch ----------------
extern "C" void kernel_launch(void* const* d_in, const int* in_sizes, int n_in,
                              void* d_out, int out_size) {
    const float* hak    = (const float*)d_in[0];
    const float* Hr     = (const float*)d_in[1];
    const float* hidden = (const float*)d_in[2];
    const float* Wf     = (const float*)d_in[3];
    const float* bf     = (const float*)d_in[4];
    const float* Wfn    = (const float*)d_in[5];
    const float* bw     = (const float*)d_in[6];
    // d_in[7] = beta_b (scalar): softmax/log_softmax shift-invariant -> unused
    const float* Wih    = (const float*)d_in[8];
    const float* Whh    = (const float*)d_in[9];
    const float* bih    = (const float*)d_in[10];
    const float* bhh    = (const float*)d_in[11];
    float* out = (float*)d_out;

    static int smem_set = 0;
    if (!smem_set) {
        cudaFuncSetAttribute(k_gemm_tc, cudaFuncAttributeMaxDynamicSharedMemorySize, GEMM_SMEM);
        cudaFuncSetAttribute(k_scores_tc, cudaFuncAttributeMaxDynamicSharedMemorySize, SC_SMEM);
        smem_set = 1;
    }

    k_small<<<320, 256>>>(hak, Wf, bf, Whh, bih, bhh);
    k_scores_tc<<<P / 4, 256, SC_SMEM>>>(Hr, Wfn, bw);
    k_softmax<<<B, 256>>>(out);
    k_gemm_tc<<<dim3(4, NCHUNK), 256, GEMM_SMEM>>>(Wih, Hr);
    k_fin<<<H, 256>>>(hidden, out);
}

// round 11
// speedup vs baseline: 2.5292x; 1.0259x over previous
#include <cuda_runtime.h>
#include <cstdint>
#include <math.h>

// Problem constants
#define H 128
#define P 512
#define B 32
#define K4H 512          // 4*H
#define KBIG 65536       // P*H
#define NCHUNK 111       // 4 j-tiles * 111 = 444 CTAs = 3 CTA/SM, one wave
#define CHUNKS 2048      // KBIG / 32 (k-chunks of 32 floats)
#define STAGES 3

// k_gemm_tc smem layout (A rows padded to 36 floats: conflict-free frag LDS)
#define A_STAGE 18432               // 128 rows * 36 floats * 4B
#define B_STAGE 4608                // 32 rows * 36 floats * 4B
#define OFF_BETA 0                  // 32*17 floats = 2176 B
#define OFF_BC   2304               // 512 uint2 = 4096 B (tf32+beta B tile, frag order)
#define OFF_A    6400
#define OFF_B    (OFF_A + STAGES * A_STAGE)          // 61696
#define GEMM_SMEM (OFF_B + STAGES * B_STAGE)         // 75520 (x3 CTA = 226.6KB/SM)

// k_scores_tc smem layout
#define SC_OFF_A   0                                 // 4 chunks * 18432 = 73728
#define SC_OFF_B   73728                             // 4 p * 18432 = 73728
#define SC_OFF_FB  147456                            // fbs_t[128][33] = 16896
#define SC_OFF_RED 164352                            // 4 p * 8 warps * 32 * 4B = 4096
#define SC_OFF_BC  168448                            // 4 chunks * 512 uint2 = 16384
#define SC_SMEM    184832

// ---------------- scratch (device globals; device-code use ONLY) ----------------
__device__ float g_fb[B * H];
__device__ float g_scores[B * P];
__device__ float g_beta[B * P];
__device__ float g_gpart[NCHUNK * K4H * B];          // 7.27 MB
__device__ float g_gates[K4H * B];

// ---------------- helpers ----------------
__device__ __forceinline__ float fsigmoid(float x) { return 1.0f / (1.0f + __expf(-x)); }
__device__ __forceinline__ float ftanh(float x) {
    float ax = fabsf(x);
    float e  = __expf(2.0f * ax);
    float t  = 1.0f - 2.0f / (e + 1.0f);
    return copysignf(t, x);
}
__device__ __forceinline__ uint32_t f2tf(float x) {
    uint32_t r;
    asm("cvt.rna.tf32.f32 %0, %1;" : "=r"(r) : "f"(x));
    return r;
}
__device__ __forceinline__ void mma_tf32(float* c, uint32_t a0, uint32_t a1,
                                         uint32_t a2, uint32_t a3,
                                         uint32_t b0, uint32_t b1) {
    asm volatile(
        "mma.sync.aligned.m16n8k8.row.col.f32.tf32.tf32.f32 "
        "{%0,%1,%2,%3}, {%4,%5,%6,%7}, {%8,%9}, {%0,%1,%2,%3};"
        : "+f"(c[0]), "+f"(c[1]), "+f"(c[2]), "+f"(c[3])
        : "r"(a0), "r"(a1), "r"(a2), "r"(a3), "r"(b0), "r"(b1));
}
__device__ __forceinline__ uint32_t smem_addr(const void* p) {
    uint32_t a;
    asm("{ .reg .u64 t; cvta.to.shared.u64 t, %1; cvt.u32.u64 %0, t; }" : "=r"(a) : "l"(p));
    return a;
}
__device__ __forceinline__ void cpa16(uint32_t dst, const void* src) {
    asm volatile("cp.async.cg.shared.global [%0], [%1], 16;" :: "r"(dst), "l"(src));
}

// ---------------- Kernel 1: small GEMMs, 8 outputs per warp ----------------
__global__ __launch_bounds__(256, 1) void k_small(
    const float* __restrict__ hak, const float* __restrict__ Wf,
    const float* __restrict__ bf,  const float* __restrict__ Whh,
    const float* __restrict__ bih, const float* __restrict__ bhh) {
    int g = blockIdx.x * 8 + (threadIdx.x >> 5);   // warp id, 0..2559
    int l = threadIdx.x & 31;
#pragma unroll
    for (int q = 0; q < 8; ++q) {
        int t = g * 8 + q;
        const float* arow;
        const float* wrow;
        if (t < 4096) {
            int b = t >> 7, h = t & 127;
            arow = hak + b * H; wrow = Wf + h * H;
        } else {
            int idx = t - 4096;
            int j = idx >> 5, b = idx & 31;
            arow = hak + b * H; wrow = Whh + j * H;
        }
        float4 a = *(const float4*)(arow + l * 4);
        float4 v = *(const float4*)(wrow + l * 4);
        float s = a.x * v.x + a.y * v.y + a.z * v.z + a.w * v.w;
#pragma unroll
        for (int o = 16; o > 0; o >>= 1) s += __shfl_xor_sync(0xffffffffu, s, o);
        if (l == 0) {
            if (t < 4096) {
                int b = t >> 7, h = t & 127;
                g_fb[b * H + h] = s + bf[h];
            } else {
                int idx = t - 4096;
                int j = idx >> 5, b = idx & 31;
                g_gates[j * B + b] = s + bih[j] + bhh[j];
            }
        }
    }
}

// ---------------- Kernel 2: tf32 mma scores, preconverted operands ----------------
__global__ __launch_bounds__(256, 1) void k_scores_tc(const float* __restrict__ Hr,
                                                      const float* __restrict__ Wfn,
                                                      const float* __restrict__ bw) {
    extern __shared__ char smem[];
    int tid = threadIdx.x, wid = tid >> 5, lane = tid & 31;
    int p0 = blockIdx.x * 4;
    uint32_t sb = smem_addr(smem);

    // A (Wfn): 4096 16B cells
#pragma unroll
    for (int r = 0; r < 16; ++r) {
        int idx = tid + 256 * r;
        int chunk = idx >> 10, rem = idx & 1023;
        int row = rem >> 3, c16 = rem & 7;
        cpa16(sb + SC_OFF_A + chunk * 18432 + row * 144 + c16 * 16,
              Wfn + row * H + chunk * 32 + c16 * 4);
    }
    asm volatile("cp.async.commit_group;");
    // B tiles, one group per p
#pragma unroll
    for (int p = 0; p < 4; ++p) {
#pragma unroll
        for (int r = 0; r < 4; ++r) {
            int idx = tid + 256 * r;
            int chunk = idx >> 8, rem = idx & 255;
            int row = rem >> 3, c16 = rem & 7;
            cpa16(sb + SC_OFF_B + p * 18432 + chunk * 4608 + row * 144 + c16 * 16,
                  Hr + (p0 + p) * (B * H) + row * H + chunk * 32 + c16 * 4);
        }
        asm volatile("cp.async.commit_group;");
    }
    float* fbs_t = (float*)(smem + SC_OFF_FB);
    for (int i = tid; i < B * H; i += 256) {
        int b = i >> 7, h = i & 127;
        fbs_t[h * 33 + b] = g_fb[i];
    }
    float* red = (float*)(smem + SC_OFF_RED);
    uint2* BcU = (uint2*)(smem + SC_OFF_BC);

    int r4 = lane >> 2, cc = lane & 3, c2 = cc * 2;
    int row0 = wid * 16 + r4;
    float bw0 = __ldg(bw + row0), bw1 = __ldg(bw + row0 + 8);

#pragma unroll
    for (int p = 0; p < 4; ++p) {
        if (p == 0)      asm volatile("cp.async.wait_group 3;");
        else if (p == 1) asm volatile("cp.async.wait_group 2;");
        else if (p == 2) asm volatile("cp.async.wait_group 1;");
        else             asm volatile("cp.async.wait_group 0;");
        __syncthreads();   // raw tiles landed (p=0: also A + fbs_t)

        if (p == 0) {
            // one-time in-place A conversion to tf32 bits
            float* Af = (float*)(smem + SC_OFF_A);
            uint32_t* Au = (uint32_t*)(smem + SC_OFF_A);
            for (int i = tid; i < 4 * 4608; i += 256) Au[i] = f2tf(Af[i]);
        }
        // preconvert this p's B (4 chunks) into fragment-ordered tf32
        {
            const float* Braw = (const float*)(smem + SC_OFF_B + p * 18432);
#pragma unroll
            for (int q = 0; q < 8; ++q) {
                int f = tid + q * 256;            // 0..2047
                int chunk = f >> 9, fr = f & 511;
                int ks = fr >> 7, rem = fr & 127;
                int nt = rem >> 5, r4p = (rem >> 2) & 7, ccp = fr & 3;
                int n = nt * 8 + r4p;
                const float* src = Braw + chunk * 1152 + n * 36 + ks * 8 + ccp;
                uint2 w;
                w.x = f2tf(src[0]);
                w.y = f2tf(src[4]);
                BcU[f] = w;
            }
        }
        __syncthreads();   // converted A + Bc ready

        float acc[4][4];
#pragma unroll
        for (int i = 0; i < 4; ++i)
#pragma unroll
            for (int j = 0; j < 4; ++j) acc[i][j] = 0.0f;

#pragma unroll
        for (int chunk = 0; chunk < 4; ++chunk) {
            const uint32_t* Au = (const uint32_t*)(smem + SC_OFF_A + chunk * 18432);
            const uint2* Bc = BcU + chunk * 512;
#pragma unroll
            for (int ks = 0; ks < 4; ++ks) {
                int k0 = ks * 8;
                uint32_t a0 = Au[row0 * 36 + k0 + cc];
                uint32_t a1 = Au[(row0 + 8) * 36 + k0 + cc];
                uint32_t a2 = Au[row0 * 36 + k0 + cc + 4];
                uint32_t a3 = Au[(row0 + 8) * 36 + k0 + cc + 4];
#pragma unroll
                for (int nt = 0; nt < 4; ++nt) {
                    uint2 bv2 = Bc[ks * 128 + nt * 32 + (r4 << 2) + cc];
                    mma_tf32(acc[nt], a0, a1, a2, a3, bv2.x, bv2.y);
                }
            }
        }
        // epilogue: tanh + bw weight; per-warp partial into per-p red
#pragma unroll
        for (int nt = 0; nt < 4; ++nt) {
            int col0 = nt * 8 + c2;
            float cs0 = ftanh(acc[nt][0] + fbs_t[row0 * 33 + col0]) * bw0
                      + ftanh(acc[nt][2] + fbs_t[(row0 + 8) * 33 + col0]) * bw1;
            float cs1 = ftanh(acc[nt][1] + fbs_t[row0 * 33 + col0 + 1]) * bw0
                      + ftanh(acc[nt][3] + fbs_t[(row0 + 8) * 33 + col0 + 1]) * bw1;
#pragma unroll
            for (int o = 4; o < 32; o <<= 1) {
                cs0 += __shfl_xor_sync(0xffffffffu, cs0, o);
                cs1 += __shfl_xor_sync(0xffffffffu, cs1, o);
            }
            if (r4 == 0) {
                red[p * 256 + wid * 32 + col0] = cs0;
                red[p * 256 + wid * 32 + col0 + 1] = cs1;
            }
        }
    }
    __syncthreads();
    if (tid < 128) {
        int p = tid >> 5, bb = tid & 31;
        float s = 0.0f;
#pragma unroll
        for (int w = 0; w < 8; ++w) s += red[p * 256 + w * 32 + bb];
        g_scores[bb * P + p0 + p] = s;   // beta_b omitted: softmax shift-invariant
    }
}

// ---------------- Kernel 3: softmax + logp ----------------
__global__ __launch_bounds__(256, 1) void k_softmax(float* __restrict__ out) {
    __shared__ float sm[256];
    int b = blockIdx.x;
    int tid = threadIdx.x;
    float s0 = g_scores[b * P + tid];
    float s1 = g_scores[b * P + tid + 256];
    sm[tid] = fmaxf(s0, s1);
    __syncthreads();
    for (int o = 128; o > 0; o >>= 1) {
        if (tid < o) sm[tid] = fmaxf(sm[tid], sm[tid + o]);
        __syncthreads();
    }
    float mx = sm[0];
    __syncthreads();
    float e0 = __expf(s0 - mx), e1 = __expf(s1 - mx);
    sm[tid] = e0 + e1;
    __syncthreads();
    for (int o = 128; o > 0; o >>= 1) {
        if (tid < o) sm[tid] += sm[tid + o];
        __syncthreads();
    }
    float Z = sm[0];
    float lz = __logf(Z);
    float inv = 1.0f / Z;
    g_beta[b * P + tid] = e0 * inv;
    g_beta[b * P + tid + 256] = e1 * inv;
    out[2 * B * H + b * P + tid] = s0 - mx - lz;
    out[2 * B * H + b * P + tid + 256] = s1 - mx - lz;
}

// ---------------- Kernel 4: tf32 mma split-K GEMM ----------------
// 128 threads / 4 warps, M=32 rows per warp (2 m16 tiles): B fragments reused
// across both m-tiles -> half the smem B traffic vs 8-warp layout.
__global__ __launch_bounds__(128, 3) void k_gemm_tc(const float* __restrict__ Wih,
                                                    const float* __restrict__ Hr) {
    extern __shared__ char smem[];
    int tid = threadIdx.x, wid = tid >> 5, lane = tid & 31;
    int jb = blockIdx.x * 128;
    int cch = blockIdx.y;
    int c0 = (cch * CHUNKS) / NCHUNK, c1 = ((cch + 1) * CHUNKS) / NCHUNK;
    int total = c1 - c0;   // 18 or 19
    int p0 = c0 >> 2;

    // cp.async mapping: A 1024 cells -> 8/thread; B 256 cells -> 2/thread
    const float* aptr[8];
    uint32_t adst[8];
#pragma unroll
    for (int r = 0; r < 8; ++r) {
        int seg = tid + 128 * r;
        int row = seg >> 3, c16 = seg & 7;
        aptr[r] = Wih + (size_t)(jb + row) * KBIG + c16 * 4;
        adst[r] = row * 144 + c16 * 16;
    }
    int bb0 = tid >> 3, bb1 = bb0 + 16;       // rows 0..15, 16..31
    int bcol = (tid & 7) * 4;
    const float* bptr0 = Hr + bb0 * H + bcol;
    const float* bptr1 = Hr + bb1 * H + bcol;
    uint32_t bdst0 = bb0 * 144 + (tid & 7) * 16;
    uint32_t bdst1 = bb1 * 144 + (tid & 7) * 16;
    uint32_t sb = smem_addr(smem);

    auto issue = [&](int chunk, int st) {
#pragma unroll
        for (int r = 0; r < 8; ++r)
            cpa16(sb + OFF_A + st * A_STAGE + adst[r], aptr[r] + chunk * 32);
        int pp = chunk >> 2, h0 = (chunk & 3) * 32;
        cpa16(sb + OFF_B + st * B_STAGE + bdst0, bptr0 + pp * (B * H) + h0);
        cpa16(sb + OFF_B + st * B_STAGE + bdst1, bptr1 + pp * (B * H) + h0);
        asm volatile("cp.async.commit_group;");
    };

    issue(c0 + 0, 0);
    issue(c0 + 1, 1);

    float* bsl = (float*)(smem + OFF_BETA);   // bsl[b*17 + (p-p0)]
    {
        int np = ((c1 - 1) >> 2) - p0 + 1;    // <= 6
        for (int t = tid; t < 32 * 17; t += 128) {
            int b = t / 17, pi = t - b * 17;
            if (pi < np) bsl[t] = g_beta[b * P + p0 + pi];
        }
    }
    uint2* BcU = (uint2*)(smem + OFF_BC);

    float acc[2][4][4];
#pragma unroll
    for (int m = 0; m < 2; ++m)
#pragma unroll
        for (int i = 0; i < 4; ++i)
#pragma unroll
            for (int j = 0; j < 4; ++j) acc[m][i][j] = 0.0f;

    // preconvert-thread decomposition (512 uint2 / 128 threads = 4 each)
    int pc_ks[4], pc_n[4], pc_cc[4];
#pragma unroll
    for (int q = 0; q < 4; ++q) {
        int f = tid + q * 128;
        pc_ks[q] = f >> 7;
        int rem = f & 127;
        pc_n[q] = (rem >> 5) * 8 + ((rem >> 2) & 7);
        pc_cc[q] = f & 3;
    }

    int r4 = lane >> 2, cc = lane & 3;
    int rowb = wid * 32 + r4;
    for (int i = 0; i < total; ++i) {
        int st = i % STAGES;
        if (i == total - 1) asm volatile("cp.async.wait_group 0;");
        else                asm volatile("cp.async.wait_group 1;");
        __syncthreads();   // stage st raw landed; stage (i+2)%S raw free
        if (i + 2 < total) issue(c0 + i + 2, (i + 2) % STAGES);

        // cooperative B preconvert: tf32 + beta, fragment order
        {
            int pi = ((c0 + i) >> 2) - p0;
            const float* Braw = (const float*)(smem + OFF_B + st * B_STAGE);
#pragma unroll
            for (int q = 0; q < 4; ++q) {
                float bv = bsl[pc_n[q] * 17 + pi];
                const float* src = Braw + pc_n[q] * 36 + pc_ks[q] * 8 + pc_cc[q];
                uint2 w;
                w.x = f2tf(src[0] * bv);
                w.y = f2tf(src[4] * bv);
                BcU[tid + q * 128] = w;
            }
        }
        __syncthreads();   // Bc ready

        const float* As = (const float*)(smem + OFF_A + st * A_STAGE);
#pragma unroll
        for (int ks = 0; ks < 4; ++ks) {
            int k0 = ks * 8;
            uint32_t a00 = f2tf(As[rowb * 36 + k0 + cc]);
            uint32_t a01 = f2tf(As[(rowb + 8) * 36 + k0 + cc]);
            uint32_t a02 = f2tf(As[rowb * 36 + k0 + cc + 4]);
            uint32_t a03 = f2tf(As[(rowb + 8) * 36 + k0 + cc + 4]);
            uint32_t a10 = f2tf(As[(rowb + 16) * 36 + k0 + cc]);
            uint32_t a11 = f2tf(As[(rowb + 24) * 36 + k0 + cc]);
            uint32_t a12 = f2tf(As[(rowb + 16) * 36 + k0 + cc + 4]);
            uint32_t a13 = f2tf(As[(rowb + 24) * 36 + k0 + cc + 4]);
#pragma unroll
            for (int nt = 0; nt < 4; ++nt) {
                uint2 bv2 = BcU[ks * 128 + nt * 32 + (r4 << 2) + cc];
                mma_tf32(acc[0][nt], a00, a01, a02, a03, bv2.x, bv2.y);
                mma_tf32(acc[1][nt], a10, a11, a12, a13, bv2.x, bv2.y);
            }
        }
    }

    int c2 = (lane & 3) * 2;
#pragma unroll
    for (int m = 0; m < 2; ++m) {
#pragma unroll
        for (int nt = 0; nt < 4; ++nt) {
            int col = nt * 8 + c2;
            int row0 = jb + wid * 32 + m * 16 + r4;
            *(float2*)&g_gpart[(cch * K4H + row0) * B + col] =
                make_float2(acc[m][nt][0], acc[m][nt][1]);
            *(float2*)&g_gpart[(cch * K4H + row0 + 8) * B + col] =
                make_float2(acc[m][nt][2], acc[m][nt][3]);
        }
    }
}

// ---------------- Kernel 5: fused split-K reduce + LSTM (1 h-row per block) ----------------
__global__ __launch_bounds__(256, 1) void k_fin(const float* __restrict__ hidden,
                                                float* __restrict__ out) {
    __shared__ float red[8][4][32];
    int b = threadIdx.x & 31;
    int s = threadIdx.x >> 5;            // slice 0..7
    int h = blockIdx.x;                  // 0..127
    float acc[4] = {0.f, 0.f, 0.f, 0.f};
    int cbeg = s * 14;
    int cend = cbeg + 14 < NCHUNK ? cbeg + 14 : NCHUNK;
    for (int c = cbeg; c < cend; ++c) {
#pragma unroll
        for (int gi = 0; gi < 4; ++gi)
            acc[gi] += g_gpart[(c * K4H + gi * H + h) * B + b];
    }
#pragma unroll
    for (int gi = 0; gi < 4; ++gi) red[s][gi][b] = acc[gi];
    __syncthreads();
    if (threadIdx.x < 32) {
        float sg[4];
#pragma unroll
        for (int gi = 0; gi < 4; ++gi) {
            float v = g_gates[(gi * H + h) * B + b];
#pragma unroll
            for (int w = 0; w < 8; ++w) v += red[w][gi][b];
            sg[gi] = v;
        }
        float cv = fsigmoid(sg[1]) * hidden[b * H + h] + fsigmoid(sg[0]) * ftanh(sg[2]);
        float hn = fsigmoid(sg[3]) * ftanh(cv);
        out[b * H + h] = hn;
        out[B * H + b * H + h] = cv;
    }
}

// ---------------- launch ----------------
extern "C" void kernel_launch(void* const* d_in, const int* in_sizes, int n_in,
                              void* d_out, int out_size) {
    const float* hak    = (const float*)d_in[0];
    const float* Hr     = (const float*)d_in[1];
    const float* hidden = (const float*)d_in[2];
    const float* Wf     = (const float*)d_in[3];
    const float* bf     = (const float*)d_in[4];
    const float* Wfn    = (const float*)d_in[5];
    const float* bw     = (const float*)d_in[6];
    // d_in[7] = beta_b (scalar): softmax/log_softmax shift-invariant -> unused
    const float* Wih    = (const float*)d_in[8];
    const float* Whh    = (const float*)d_in[9];
    const float* bih    = (const float*)d_in[10];
    const float* bhh    = (const float*)d_in[11];
    float* out = (float*)d_out;

    static int smem_set = 0;
    if (!smem_set) {
        cudaFuncSetAttribute(k_gemm_tc, cudaFuncAttributeMaxDynamicSharedMemorySize, GEMM_SMEM);
        cudaFuncSetAttribute(k_scores_tc, cudaFuncAttributeMaxDynamicSharedMemorySize, SC_SMEM);
        smem_set = 1;
    }

    k_small<<<320, 256>>>(hak, Wf, bf, Whh, bih, bhh);
    k_scores_tc<<<P / 4, 256, SC_SMEM>>>(Hr, Wfn, bw);
    k_softmax<<<B, 256>>>(out);
    k_gemm_tc<<<dim3(4, NCHUNK), 128, GEMM_SMEM>>>(Wih, Hr);
    k_fin<<<H, 256>>>(hidden, out);
}

// round 14
// speedup vs baseline: 2.5412x; 1.0047x over previous
#include <cuda_runtime.h>
#include <cstdint>
#include <math.h>

// Problem constants
#define H 128
#define P 512
#define B 32
#define K4H 512          // 4*H
#define KBIG 65536       // P*H
#define NCHUNK 111       // 4 j-tiles * 111 = 444 CTAs = 3 CTA/SM, one wave
#define CHUNKS 2048      // KBIG / 32 (k-chunks of 32 floats)
#define STAGES 3

// k_gemm_tc smem layout (A rows padded to 36 floats: conflict-free frag LDS)
#define A_STAGE 18432               // 128 rows * 36 floats * 4B
#define B_STAGE 4608                // 32 rows * 36 floats * 4B
#define OFF_BETA 0                  // 32*17 floats = 2176 B
#define OFF_BC   2304               // 512 uint2 = 4096 B (tf32+beta B tile, frag order)
#define OFF_A    6400
#define OFF_B    (OFF_A + STAGES * A_STAGE)          // 61696
#define GEMM_SMEM (OFF_B + STAGES * B_STAGE)         // 75520 (x3 CTA = 226.6KB/SM)

// k_scores_tc smem layout
#define SC_OFF_A   0                                 // 4 chunks * 18432 = 73728
#define SC_OFF_B   73728                             // 4 p * 18432 = 73728
#define SC_OFF_FB  147456                            // fbs_t[128][33] = 16896
#define SC_OFF_RED 164352                            // 4 p * 8 warps * 32 * 4B = 4096
#define SC_OFF_BC  168448                            // 4 chunks * 512 uint2 = 16384
#define SC_SMEM    184832

// ---------------- scratch (device globals; device-code use ONLY) ----------------
__device__ float g_scores[B * P];
__device__ float g_beta[B * P];
__device__ float g_gpart[NCHUNK * K4H * B];          // 7.27 MB

// ---------------- helpers ----------------
__device__ __forceinline__ float fsigmoid(float x) { return 1.0f / (1.0f + __expf(-x)); }
__device__ __forceinline__ float ftanh(float x) {
    float ax = fabsf(x);
    float e  = __expf(2.0f * ax);
    float t  = 1.0f - 2.0f / (e + 1.0f);
    return copysignf(t, x);
}
__device__ __forceinline__ uint32_t f2tf(float x) {
    uint32_t r;
    asm("cvt.rna.tf32.f32 %0, %1;" : "=r"(r) : "f"(x));
    return r;
}
__device__ __forceinline__ void mma_tf32(float* c, uint32_t a0, uint32_t a1,
                                         uint32_t a2, uint32_t a3,
                                         uint32_t b0, uint32_t b1) {
    asm volatile(
        "mma.sync.aligned.m16n8k8.row.col.f32.tf32.tf32.f32 "
        "{%0,%1,%2,%3}, {%4,%5,%6,%7}, {%8,%9}, {%0,%1,%2,%3};"
        : "+f"(c[0]), "+f"(c[1]), "+f"(c[2]), "+f"(c[3])
        : "r"(a0), "r"(a1), "r"(a2), "r"(a3), "r"(b0), "r"(b1));
}
__device__ __forceinline__ uint32_t smem_addr(const void* p) {
    uint32_t a;
    asm("{ .reg .u64 t; cvta.to.shared.u64 t, %1; cvt.u32.u64 %0, t; }" : "=r"(a) : "l"(p));
    return a;
}
__device__ __forceinline__ void cpa16(uint32_t dst, const void* src) {
    asm volatile("cp.async.cg.shared.global [%0], [%1], 16;" :: "r"(dst), "l"(src));
}

// ---------------- Kernel 1: tf32 mma scores + in-block fb ----------------
// Per block: 4 consecutive p. fb = hak @ Wf^T + bf computed first via MMA
// (A slot holds Wf, B0 holds hak), then slots reloaded with Wfn / Hr[p0].
// Process order p1,p2,p3,p0 so fb compute overlaps Hr prefetch.
__global__ __launch_bounds__(256, 1) void k_scores_tc(const float* __restrict__ Hr,
                                                      const float* __restrict__ Wfn,
                                                      const float* __restrict__ Wf,
                                                      const float* __restrict__ hak,
                                                      const float* __restrict__ bf,
                                                      const float* __restrict__ bw) {
    extern __shared__ char smem[];
    int tid = threadIdx.x, wid = tid >> 5, lane = tid & 31;
    int p0 = blockIdx.x * 4;
    uint32_t sb = smem_addr(smem);

    int r4 = lane >> 2, cc = lane & 3, c2 = cc * 2;
    int row0 = wid * 16 + r4;

    // G0: Wf -> A slot (4096 cells), hak -> B0 (1024 cells)
#pragma unroll
    for (int r = 0; r < 16; ++r) {
        int idx = tid + 256 * r;
        int chunk = idx >> 10, rem = idx & 1023;
        int row = rem >> 3, c16 = rem & 7;
        cpa16(sb + SC_OFF_A + chunk * 18432 + row * 144 + c16 * 16,
              Wf + row * H + chunk * 32 + c16 * 4);
    }
#pragma unroll
    for (int r = 0; r < 4; ++r) {
        int idx = tid + 256 * r;
        int chunk = idx >> 8, rem = idx & 255;
        int row = rem >> 3, c16 = rem & 7;
        cpa16(sb + SC_OFF_B + chunk * 4608 + row * 144 + c16 * 16,
              hak + row * H + chunk * 32 + c16 * 4);
    }
    asm volatile("cp.async.commit_group;");   // G0
    // G1..G3: Hr[p1..p3] -> B1..B3
#pragma unroll
    for (int p = 1; p < 4; ++p) {
#pragma unroll
        for (int r = 0; r < 4; ++r) {
            int idx = tid + 256 * r;
            int chunk = idx >> 8, rem = idx & 255;
            int row = rem >> 3, c16 = rem & 7;
            cpa16(sb + SC_OFF_B + p * 18432 + chunk * 4608 + row * 144 + c16 * 16,
                  Hr + (p0 + p) * (B * H) + row * H + chunk * 32 + c16 * 4);
        }
        asm volatile("cp.async.commit_group;");
    }

    float* fbs_t = (float*)(smem + SC_OFF_FB);
    float* red = (float*)(smem + SC_OFF_RED);
    uint2* BcU = (uint2*)(smem + SC_OFF_BC);

    float bw0 = __ldg(bw + row0), bw1 = __ldg(bw + row0 + 8);
    float bf0 = __ldg(bf + row0), bf8 = __ldg(bf + row0 + 8);

    // ---- fb phase: wait G0, compute fb = Wf @ hak^T via on-the-fly tf32 MMA ----
    asm volatile("cp.async.wait_group 3;");   // G0 done (G1..G3 may pend)
    __syncthreads();
    {
        float accf[4][4];
#pragma unroll
        for (int i = 0; i < 4; ++i)
#pragma unroll
            for (int j = 0; j < 4; ++j) accf[i][j] = 0.0f;
#pragma unroll
        for (int chunk = 0; chunk < 4; ++chunk) {
            const float* As = (const float*)(smem + SC_OFF_A + chunk * 18432);
            const float* Bs = (const float*)(smem + SC_OFF_B + chunk * 4608);
#pragma unroll
            for (int ks = 0; ks < 4; ++ks) {
                int k0 = ks * 8;
                uint32_t a0 = f2tf(As[row0 * 36 + k0 + cc]);
                uint32_t a1 = f2tf(As[(row0 + 8) * 36 + k0 + cc]);
                uint32_t a2 = f2tf(As[row0 * 36 + k0 + cc + 4]);
                uint32_t a3 = f2tf(As[(row0 + 8) * 36 + k0 + cc + 4]);
#pragma unroll
                for (int nt = 0; nt < 4; ++nt) {
                    uint32_t b0 = f2tf(Bs[(nt * 8 + r4) * 36 + k0 + cc]);
                    uint32_t b1 = f2tf(Bs[(nt * 8 + r4) * 36 + k0 + cc + 4]);
                    mma_tf32(accf[nt], a0, a1, a2, a3, b0, b1);
                }
            }
        }
        // fbs_t[h*33 + b] = fb[b][h] = acc + bf[h]
#pragma unroll
        for (int nt = 0; nt < 4; ++nt) {
            int col = nt * 8 + c2;
            fbs_t[row0 * 33 + col]           = accf[nt][0] + bf0;
            fbs_t[row0 * 33 + col + 1]       = accf[nt][1] + bf0;
            fbs_t[(row0 + 8) * 33 + col]     = accf[nt][2] + bf8;
            fbs_t[(row0 + 8) * 33 + col + 1] = accf[nt][3] + bf8;
        }
    }
    __syncthreads();   // all reads of A(Wf)/B0(hak) done -> safe to overwrite

    // G4: Wfn -> A ; G5: Hr[p0] -> B0
#pragma unroll
    for (int r = 0; r < 16; ++r) {
        int idx = tid + 256 * r;
        int chunk = idx >> 10, rem = idx & 1023;
        int row = rem >> 3, c16 = rem & 7;
        cpa16(sb + SC_OFF_A + chunk * 18432 + row * 144 + c16 * 16,
              Wfn + row * H + chunk * 32 + c16 * 4);
    }
    asm volatile("cp.async.commit_group;");   // G4
#pragma unroll
    for (int r = 0; r < 4; ++r) {
        int idx = tid + 256 * r;
        int chunk = idx >> 8, rem = idx & 255;
        int row = rem >> 3, c16 = rem & 7;
        cpa16(sb + SC_OFF_B + chunk * 4608 + row * 144 + c16 * 16,
              Hr + p0 * (B * H) + row * H + chunk * 32 + c16 * 4);
    }
    asm volatile("cp.async.commit_group;");   // G5

    // ---- main p loop, order {1,2,3,0} ----
#pragma unroll
    for (int it = 0; it < 4; ++it) {
        int p = (it + 1) & 3;   // 1,2,3,0
        if (it < 3) asm volatile("cp.async.wait_group 1;");   // G0..G4 done
        else        asm volatile("cp.async.wait_group 0;");   // all done (B0=Hr[p0])
        __syncthreads();

        if (it == 0) {
            // one-time in-place A (Wfn) conversion to tf32 bits
            float* Af = (float*)(smem + SC_OFF_A);
            uint32_t* Au = (uint32_t*)(smem + SC_OFF_A);
            for (int i = tid; i < 4 * 4608; i += 256) Au[i] = f2tf(Af[i]);
        }
        // preconvert this p's B (4 chunks) into fragment-ordered tf32
        {
            const float* Braw = (const float*)(smem + SC_OFF_B + p * 18432);
#pragma unroll
            for (int q = 0; q < 2; ++q) {
                int f = tid + q * 256;            // 0..511 (within-chunk frag id)
                int ks = f >> 7;
                int rem = f & 127;
                int nt = rem >> 5, r4p = (rem >> 2) & 7, ccp = f & 3;
                int n = nt * 8 + r4p;
#pragma unroll
                for (int chunk = 0; chunk < 4; ++chunk) {
                    const float* src = Braw + chunk * 1152 + n * 36 + ks * 8 + ccp;
                    uint2 w;
                    w.x = f2tf(src[0]);
                    w.y = f2tf(src[4]);
                    BcU[chunk * 512 + f] = w;
                }
            }
        }
        __syncthreads();   // converted A + Bc ready

        float acc[4][4];
#pragma unroll
        for (int i = 0; i < 4; ++i)
#pragma unroll
            for (int j = 0; j < 4; ++j) acc[i][j] = 0.0f;

#pragma unroll
        for (int chunk = 0; chunk < 4; ++chunk) {
            const uint32_t* Au = (const uint32_t*)(smem + SC_OFF_A + chunk * 18432);
            const uint2* Bc = BcU + chunk * 512;
#pragma unroll
            for (int ks = 0; ks < 4; ++ks) {
                int k0 = ks * 8;
                uint32_t a0 = Au[row0 * 36 + k0 + cc];
                uint32_t a1 = Au[(row0 + 8) * 36 + k0 + cc];
                uint32_t a2 = Au[row0 * 36 + k0 + cc + 4];
                uint32_t a3 = Au[(row0 + 8) * 36 + k0 + cc + 4];
#pragma unroll
                for (int nt = 0; nt < 4; ++nt) {
                    uint2 bv2 = Bc[ks * 128 + nt * 32 + (r4 << 2) + cc];
                    mma_tf32(acc[nt], a0, a1, a2, a3, bv2.x, bv2.y);
                }
            }
        }
        // epilogue: tanh + bw weight; per-warp partial into per-p red
#pragma unroll
        for (int nt = 0; nt < 4; ++nt) {
            int col0 = nt * 8 + c2;
            float cs0 = ftanh(acc[nt][0] + fbs_t[row0 * 33 + col0]) * bw0
                      + ftanh(acc[nt][2] + fbs_t[(row0 + 8) * 33 + col0]) * bw1;
            float cs1 = ftanh(acc[nt][1] + fbs_t[row0 * 33 + col0 + 1]) * bw0
                      + ftanh(acc[nt][3] + fbs_t[(row0 + 8) * 33 + col0 + 1]) * bw1;
#pragma unroll
            for (int o = 4; o < 32; o <<= 1) {
                cs0 += __shfl_xor_sync(0xffffffffu, cs0, o);
                cs1 += __shfl_xor_sync(0xffffffffu, cs1, o);
            }
            if (r4 == 0) {
                red[p * 256 + wid * 32 + col0] = cs0;
                red[p * 256 + wid * 32 + col0 + 1] = cs1;
            }
        }
        __syncthreads();   // Bc reuse next iter: all warps done reading
    }
    if (tid < 128) {
        int p = tid >> 5, bb = tid & 31;
        float s = 0.0f;
#pragma unroll
        for (int w = 0; w < 8; ++w) s += red[p * 256 + w * 32 + bb];
        g_scores[bb * P + p0 + p] = s;   // beta_b omitted: softmax shift-invariant
    }
}

// ---------------- Kernel 2: softmax + logp ----------------
__global__ __launch_bounds__(256, 1) void k_softmax(float* __restrict__ out) {
    __shared__ float sm[256];
    int b = blockIdx.x;
    int tid = threadIdx.x;
    float s0 = g_scores[b * P + tid];
    float s1 = g_scores[b * P + tid + 256];
    sm[tid] = fmaxf(s0, s1);
    __syncthreads();
    for (int o = 128; o > 0; o >>= 1) {
        if (tid < o) sm[tid] = fmaxf(sm[tid], sm[tid + o]);
        __syncthreads();
    }
    float mx = sm[0];
    __syncthreads();
    float e0 = __expf(s0 - mx), e1 = __expf(s1 - mx);
    sm[tid] = e0 + e1;
    __syncthreads();
    for (int o = 128; o > 0; o >>= 1) {
        if (tid < o) sm[tid] += sm[tid + o];
        __syncthreads();
    }
    float Z = sm[0];
    float lz = __logf(Z);
    float inv = 1.0f / Z;
    g_beta[b * P + tid] = e0 * inv;
    g_beta[b * P + tid + 256] = e1 * inv;
    out[2 * B * H + b * P + tid] = s0 - mx - lz;
    out[2 * B * H + b * P + tid + 256] = s1 - mx - lz;
}

// ---------------- Kernel 3: tf32 mma split-K GEMM (unchanged from R11) ----------------
__global__ __launch_bounds__(128, 3) void k_gemm_tc(const float* __restrict__ Wih,
                                                    const float* __restrict__ Hr) {
    extern __shared__ char smem[];
    int tid = threadIdx.x, wid = tid >> 5, lane = tid & 31;
    int jb = blockIdx.x * 128;
    int cch = blockIdx.y;
    int c0 = (cch * CHUNKS) / NCHUNK, c1 = ((cch + 1) * CHUNKS) / NCHUNK;
    int total = c1 - c0;   // 18 or 19
    int p0 = c0 >> 2;

    const float* aptr[8];
    uint32_t adst[8];
#pragma unroll
    for (int r = 0; r < 8; ++r) {
        int seg = tid + 128 * r;
        int row = seg >> 3, c16 = seg & 7;
        aptr[r] = Wih + (size_t)(jb + row) * KBIG + c16 * 4;
        adst[r] = row * 144 + c16 * 16;
    }
    int bb0 = tid >> 3, bb1 = bb0 + 16;
    int bcol = (tid & 7) * 4;
    const float* bptr0 = Hr + bb0 * H + bcol;
    const float* bptr1 = Hr + bb1 * H + bcol;
    uint32_t bdst0 = bb0 * 144 + (tid & 7) * 16;
    uint32_t bdst1 = bb1 * 144 + (tid & 7) * 16;
    uint32_t sb = smem_addr(smem);

    auto issue = [&](int chunk, int st) {
#pragma unroll
        for (int r = 0; r < 8; ++r)
            cpa16(sb + OFF_A + st * A_STAGE + adst[r], aptr[r] + chunk * 32);
        int pp = chunk >> 2, h0 = (chunk & 3) * 32;
        cpa16(sb + OFF_B + st * B_STAGE + bdst0, bptr0 + pp * (B * H) + h0);
        cpa16(sb + OFF_B + st * B_STAGE + bdst1, bptr1 + pp * (B * H) + h0);
        asm volatile("cp.async.commit_group;");
    };

    issue(c0 + 0, 0);
    issue(c0 + 1, 1);

    float* bsl = (float*)(smem + OFF_BETA);
    {
        int np = ((c1 - 1) >> 2) - p0 + 1;
        for (int t = tid; t < 32 * 17; t += 128) {
            int b = t / 17, pi = t - b * 17;
            if (pi < np) bsl[t] = g_beta[b * P + p0 + pi];
        }
    }
    uint2* BcU = (uint2*)(smem + OFF_BC);

    float acc[2][4][4];
#pragma unroll
    for (int m = 0; m < 2; ++m)
#pragma unroll
        for (int i = 0; i < 4; ++i)
#pragma unroll
            for (int j = 0; j < 4; ++j) acc[m][i][j] = 0.0f;

    int pc_ks[4], pc_n[4], pc_cc[4];
#pragma unroll
    for (int q = 0; q < 4; ++q) {
        int f = tid + q * 128;
        pc_ks[q] = f >> 7;
        int rem = f & 127;
        pc_n[q] = (rem >> 5) * 8 + ((rem >> 2) & 7);
        pc_cc[q] = f & 3;
    }

    int r4 = lane >> 2, cc = lane & 3;
    int rowb = wid * 32 + r4;
    for (int i = 0; i < total; ++i) {
        int st = i % STAGES;
        if (i == total - 1) asm volatile("cp.async.wait_group 0;");
        else                asm volatile("cp.async.wait_group 1;");
        __syncthreads();
        if (i + 2 < total) issue(c0 + i + 2, (i + 2) % STAGES);

        {
            int pi = ((c0 + i) >> 2) - p0;
            const float* Braw = (const float*)(smem + OFF_B + st * B_STAGE);
#pragma unroll
            for (int q = 0; q < 4; ++q) {
                float bv = bsl[pc_n[q] * 17 + pi];
                const float* src = Braw + pc_n[q] * 36 + pc_ks[q] * 8 + pc_cc[q];
                uint2 w;
                w.x = f2tf(src[0] * bv);
                w.y = f2tf(src[4] * bv);
                BcU[tid + q * 128] = w;
            }
        }
        __syncthreads();

        const float* As = (const float*)(smem + OFF_A + st * A_STAGE);
#pragma unroll
        for (int ks = 0; ks < 4; ++ks) {
            int k0 = ks * 8;
            uint32_t a00 = f2tf(As[rowb * 36 + k0 + cc]);
            uint32_t a01 = f2tf(As[(rowb + 8) * 36 + k0 + cc]);
            uint32_t a02 = f2tf(As[rowb * 36 + k0 + cc + 4]);
            uint32_t a03 = f2tf(As[(rowb + 8) * 36 + k0 + cc + 4]);
            uint32_t a10 = f2tf(As[(rowb + 16) * 36 + k0 + cc]);
            uint32_t a11 = f2tf(As[(rowb + 24) * 36 + k0 + cc]);
            uint32_t a12 = f2tf(As[(rowb + 16) * 36 + k0 + cc + 4]);
            uint32_t a13 = f2tf(As[(rowb + 24) * 36 + k0 + cc + 4]);
#pragma unroll
            for (int nt = 0; nt < 4; ++nt) {
                uint2 bv2 = BcU[ks * 128 + nt * 32 + (r4 << 2) + cc];
                mma_tf32(acc[0][nt], a00, a01, a02, a03, bv2.x, bv2.y);
                mma_tf32(acc[1][nt], a10, a11, a12, a13, bv2.x, bv2.y);
            }
        }
    }

    int c2 = (lane & 3) * 2;
#pragma unroll
    for (int m = 0; m < 2; ++m) {
#pragma unroll
        for (int nt = 0; nt < 4; ++nt) {
            int col = nt * 8 + c2;
            int row0 = jb + wid * 32 + m * 16 + r4;
            *(float2*)&g_gpart[(cch * K4H + row0) * B + col] =
                make_float2(acc[m][nt][0], acc[m][nt][1]);
            *(float2*)&g_gpart[(cch * K4H + row0 + 8) * B + col] =
                make_float2(acc[m][nt][2], acc[m][nt][3]);
        }
    }
}

// ---------------- Kernel 4: fused gates0 + split-K reduce + LSTM ----------------
// One block per h. gates0[j][b] = dot(hak[b], Whh[j]) computed here (fp32),
// j = gi*128 + h; plus biases; plus split-K partial reduction; then LSTM cell.
__global__ __launch_bounds__(256, 1) void k_fin(const float* __restrict__ hidden,
                                                const float* __restrict__ hak,
                                                const float* __restrict__ Whh,
                                                const float* __restrict__ bih,
                                                const float* __restrict__ bhh,
                                                float* __restrict__ out) {
    __shared__ float hak_s[B * 129];     // stride 129: conflict-free lane-b LDS
    __shared__ float red[8][4][32];
    __shared__ float red2[4][2][32];
    int tid = threadIdx.x;
    int b = tid & 31;
    int q = tid >> 5;                    // 0..7
    int h = blockIdx.x;                  // 0..127

    // stage hak (coalesced read, strided store)
    for (int i = tid; i < B * H; i += 256) {
        hak_s[(i >> 7) * 129 + (i & 127)] = hak[i];
    }
    __syncthreads();

    // gates0 partial: warp q -> (gi = q>>1, half = q&1), lanes over b
    {
        int gi = q >> 1, half = q & 1;
        int j = gi * H + h;
        const float4* wr = (const float4*)(Whh + j * H) + half * 16;
        float acc = 0.0f;
#pragma unroll
        for (int kk = 0; kk < 16; ++kk) {
            float4 w4 = __ldg(wr + kk);          // broadcast across lanes
            int k = half * 64 + kk * 4;
            const float* hs = &hak_s[b * 129 + k];
            acc += w4.x * hs[0] + w4.y * hs[1] + w4.z * hs[2] + w4.w * hs[3];
        }
        red2[gi][half][b] = acc;
    }

    // split-K partial reduction over g_gpart (slice q)
    {
        float acc[4] = {0.f, 0.f, 0.f, 0.f};
        int cbeg = q * 14;
        int cend = cbeg + 14 < NCHUNK ? cbeg + 14 : NCHUNK;
        for (int c = cbeg; c < cend; ++c) {
#pragma unroll
            for (int gi = 0; gi < 4; ++gi)
                acc[gi] += g_gpart[(c * K4H + gi * H + h) * B + b];
        }
#pragma unroll
        for (int gi = 0; gi < 4; ++gi) red[q][gi][b] = acc[gi];
    }
    __syncthreads();

    if (tid < 32) {
        float sg[4];
#pragma unroll
        for (int gi = 0; gi < 4; ++gi) {
            int j = gi * H + h;
            float v = __ldg(bih + j) + __ldg(bhh + j)
                    + red2[gi][0][b] + red2[gi][1][b];
#pragma unroll
            for (int w = 0; w < 8; ++w) v += red[w][gi][b];
            sg[gi] = v;
        }
        float cv = fsigmoid(sg[1]) * hidden[b * H + h] + fsigmoid(sg[0]) * ftanh(sg[2]);
        float hn = fsigmoid(sg[3]) * ftanh(cv);
        out[b * H + h] = hn;
        out[B * H + b * H + h] = cv;
    }
}

// ---------------- launch ----------------
extern "C" void kernel_launch(void* const* d_in, const int* in_sizes, int n_in,
                              void* d_out, int out_size) {
    const float* hak    = (const float*)d_in[0];
    const float* Hr     = (const float*)d_in[1];
    const float* hidden = (const float*)d_in[2];
    const float* Wf     = (const float*)d_in[3];
    const float* bf     = (const float*)d_in[4];
    const float* Wfn    = (const float*)d_in[5];
    const float* bw     = (const float*)d_in[6];
    // d_in[7] = beta_b (scalar): softmax/log_softmax shift-invariant -> unused
    const float* Wih    = (const float*)d_in[8];
    const float* Whh    = (const float*)d_in[9];
    const float* bih    = (const float*)d_in[10];
    const float* bhh    = (const float*)d_in[11];
    float* out = (float*)d_out;

    static int smem_set = 0;
    if (!smem_set) {
        cudaFuncSetAttribute(k_gemm_tc, cudaFuncAttributeMaxDynamicSharedMemorySize, GEMM_SMEM);
        cudaFuncSetAttribute(k_scores_tc, cudaFuncAttributeMaxDynamicSharedMemorySize, SC_SMEM);
        smem_set = 1;
    }

    k_scores_tc<<<P / 4, 256, SC_SMEM>>>(Hr, Wfn, Wf, hak, bf, bw);
    k_softmax<<<B, 256>>>(out);
    k_gemm_tc<<<dim3(4, NCHUNK), 128, GEMM_SMEM>>>(Wih, Hr);
    k_fin<<<H, 256>>>(hidden, hak, Whh, bih, bhh, out);
}

// round 15
// speedup vs baseline: 2.5569x; 1.0062x over previous
#include <cuda_runtime.h>
#include <cstdint>
#include <math.h>

// Problem constants
#define H 128
#define P 512
#define B 32
#define K4H 512          // 4*H
#define KBIG 65536       // P*H
#define NCHUNK 111       // 4 j-tiles * 111 = 444 CTAs = 3 CTA/SM, one wave
#define CHUNKS 2048      // KBIG / 32 (k-chunks of 32 floats)
#define STAGES 3

// k_gemm_tc smem layout (A rows padded to 36 floats: conflict-free frag LDS)
#define A_STAGE 18432               // 128 rows * 36 floats * 4B
#define B_STAGE 4608                // 32 rows * 36 floats * 4B
#define OFF_BETA 0                  // 32*17 floats = 2176 B
#define OFF_BC   2304               // 512 uint2 = 4096 B (tf32+beta B tile, frag order)
#define OFF_A    6400
#define OFF_B    (OFF_A + STAGES * A_STAGE)          // 61696
#define GEMM_SMEM (OFF_B + STAGES * B_STAGE)         // 75520 (x3 CTA = 226.6KB/SM)

// k_scores_tc smem layout
#define SC_OFF_A   0                                 // 4 chunks * 18432 = 73728
#define SC_OFF_B   73728                             // 4 p * 18432 = 73728
#define SC_OFF_FB  147456                            // fbs_t[128][33] = 16896
#define SC_OFF_RED 164352                            // 4 p * 8 warps * 32 * 4B = 4096
#define SC_OFF_BC  168448                            // 4 chunks * 512 uint2 = 16384
#define SC_SMEM    184832

// ---------------- scratch (device globals; device-code use ONLY) ----------------
__device__ float g_scores[B * P];
__device__ float g_beta[B * P];
__device__ float g_gpart[NCHUNK * K4H * B];          // 7.27 MB

// ---------------- helpers ----------------
__device__ __forceinline__ float fsigmoid(float x) { return 1.0f / (1.0f + __expf(-x)); }
__device__ __forceinline__ float ftanh(float x) {
    float ax = fabsf(x);
    float e  = __expf(2.0f * ax);
    float t  = 1.0f - 2.0f / (e + 1.0f);
    return copysignf(t, x);
}
__device__ __forceinline__ uint32_t f2tf(float x) {
    uint32_t r;
    asm("cvt.rna.tf32.f32 %0, %1;" : "=r"(r) : "f"(x));
    return r;
}
__device__ __forceinline__ void mma_tf32(float* c, uint32_t a0, uint32_t a1,
                                         uint32_t a2, uint32_t a3,
                                         uint32_t b0, uint32_t b1) {
    asm volatile(
        "mma.sync.aligned.m16n8k8.row.col.f32.tf32.tf32.f32 "
        "{%0,%1,%2,%3}, {%4,%5,%6,%7}, {%8,%9}, {%0,%1,%2,%3};"
        : "+f"(c[0]), "+f"(c[1]), "+f"(c[2]), "+f"(c[3])
        : "r"(a0), "r"(a1), "r"(a2), "r"(a3), "r"(b0), "r"(b1));
}
__device__ __forceinline__ uint32_t smem_addr(const void* p) {
    uint32_t a;
    asm("{ .reg .u64 t; cvta.to.shared.u64 t, %1; cvt.u32.u64 %0, t; }" : "=r"(a) : "l"(p));
    return a;
}
__device__ __forceinline__ void cpa16(uint32_t dst, const void* src) {
    asm volatile("cp.async.cg.shared.global [%0], [%1], 16;" :: "r"(dst), "l"(src));
}

// ---------------- Kernel 1: tf32 mma scores + in-block fb ----------------
// Per block: 4 consecutive p. fb = hak @ Wf^T + bf computed first via MMA
// (A slot holds Wf, B0 holds hak), then slots reloaded with Wfn / Hr[p0].
// Process order p1,p2,p3,p0 so fb compute overlaps Hr prefetch.
__global__ __launch_bounds__(256, 1) void k_scores_tc(const float* __restrict__ Hr,
                                                      const float* __restrict__ Wfn,
                                                      const float* __restrict__ Wf,
                                                      const float* __restrict__ hak,
                                                      const float* __restrict__ bf,
                                                      const float* __restrict__ bw) {
    extern __shared__ char smem[];
    int tid = threadIdx.x, wid = tid >> 5, lane = tid & 31;
    int p0 = blockIdx.x * 4;
    uint32_t sb = smem_addr(smem);

    int r4 = lane >> 2, cc = lane & 3, c2 = cc * 2;
    int row0 = wid * 16 + r4;

    // G0: Wf -> A slot (4096 cells), hak -> B0 (1024 cells)
#pragma unroll
    for (int r = 0; r < 16; ++r) {
        int idx = tid + 256 * r;
        int chunk = idx >> 10, rem = idx & 1023;
        int row = rem >> 3, c16 = rem & 7;
        cpa16(sb + SC_OFF_A + chunk * 18432 + row * 144 + c16 * 16,
              Wf + row * H + chunk * 32 + c16 * 4);
    }
#pragma unroll
    for (int r = 0; r < 4; ++r) {
        int idx = tid + 256 * r;
        int chunk = idx >> 8, rem = idx & 255;
        int row = rem >> 3, c16 = rem & 7;
        cpa16(sb + SC_OFF_B + chunk * 4608 + row * 144 + c16 * 16,
              hak + row * H + chunk * 32 + c16 * 4);
    }
    asm volatile("cp.async.commit_group;");   // G0
    // G1..G3: Hr[p1..p3] -> B1..B3
#pragma unroll
    for (int p = 1; p < 4; ++p) {
#pragma unroll
        for (int r = 0; r < 4; ++r) {
            int idx = tid + 256 * r;
            int chunk = idx >> 8, rem = idx & 255;
            int row = rem >> 3, c16 = rem & 7;
            cpa16(sb + SC_OFF_B + p * 18432 + chunk * 4608 + row * 144 + c16 * 16,
                  Hr + (p0 + p) * (B * H) + row * H + chunk * 32 + c16 * 4);
        }
        asm volatile("cp.async.commit_group;");
    }

    float* fbs_t = (float*)(smem + SC_OFF_FB);
    float* red = (float*)(smem + SC_OFF_RED);
    uint2* BcU = (uint2*)(smem + SC_OFF_BC);

    float bw0 = __ldg(bw + row0), bw1 = __ldg(bw + row0 + 8);
    float bf0 = __ldg(bf + row0), bf8 = __ldg(bf + row0 + 8);

    // ---- fb phase: wait G0, compute fb = Wf @ hak^T via on-the-fly tf32 MMA ----
    asm volatile("cp.async.wait_group 3;");   // G0 done (G1..G3 may pend)
    __syncthreads();
    {
        float accf[4][4];
#pragma unroll
        for (int i = 0; i < 4; ++i)
#pragma unroll
            for (int j = 0; j < 4; ++j) accf[i][j] = 0.0f;
#pragma unroll
        for (int chunk = 0; chunk < 4; ++chunk) {
            const float* As = (const float*)(smem + SC_OFF_A + chunk * 18432);
            const float* Bs = (const float*)(smem + SC_OFF_B + chunk * 4608);
#pragma unroll
            for (int ks = 0; ks < 4; ++ks) {
                int k0 = ks * 8;
                uint32_t a0 = f2tf(As[row0 * 36 + k0 + cc]);
                uint32_t a1 = f2tf(As[(row0 + 8) * 36 + k0 + cc]);
                uint32_t a2 = f2tf(As[row0 * 36 + k0 + cc + 4]);
                uint32_t a3 = f2tf(As[(row0 + 8) * 36 + k0 + cc + 4]);
#pragma unroll
                for (int nt = 0; nt < 4; ++nt) {
                    uint32_t b0 = f2tf(Bs[(nt * 8 + r4) * 36 + k0 + cc]);
                    uint32_t b1 = f2tf(Bs[(nt * 8 + r4) * 36 + k0 + cc + 4]);
                    mma_tf32(accf[nt], a0, a1, a2, a3, b0, b1);
                }
            }
        }
        // fbs_t[h*33 + b] = fb[b][h] = acc + bf[h]
#pragma unroll
        for (int nt = 0; nt < 4; ++nt) {
            int col = nt * 8 + c2;
            fbs_t[row0 * 33 + col]           = accf[nt][0] + bf0;
            fbs_t[row0 * 33 + col + 1]       = accf[nt][1] + bf0;
            fbs_t[(row0 + 8) * 33 + col]     = accf[nt][2] + bf8;
            fbs_t[(row0 + 8) * 33 + col + 1] = accf[nt][3] + bf8;
        }
    }
    __syncthreads();   // all reads of A(Wf)/B0(hak) done -> safe to overwrite

    // G4: Wfn -> A ; G5: Hr[p0] -> B0
#pragma unroll
    for (int r = 0; r < 16; ++r) {
        int idx = tid + 256 * r;
        int chunk = idx >> 10, rem = idx & 1023;
        int row = rem >> 3, c16 = rem & 7;
        cpa16(sb + SC_OFF_A + chunk * 18432 + row * 144 + c16 * 16,
              Wfn + row * H + chunk * 32 + c16 * 4);
    }
    asm volatile("cp.async.commit_group;");   // G4
#pragma unroll
    for (int r = 0; r < 4; ++r) {
        int idx = tid + 256 * r;
        int chunk = idx >> 8, rem = idx & 255;
        int row = rem >> 3, c16 = rem & 7;
        cpa16(sb + SC_OFF_B + chunk * 4608 + row * 144 + c16 * 16,
              Hr + p0 * (B * H) + row * H + chunk * 32 + c16 * 4);
    }
    asm volatile("cp.async.commit_group;");   // G5

    // ---- main p loop, order {1,2,3,0} ----
#pragma unroll
    for (int it = 0; it < 4; ++it) {
        int p = (it + 1) & 3;   // 1,2,3,0
        if (it < 3) asm volatile("cp.async.wait_group 1;");   // G0..G4 done
        else        asm volatile("cp.async.wait_group 0;");   // all done (B0=Hr[p0])
        __syncthreads();

        if (it == 0) {
            // one-time in-place A (Wfn) conversion to tf32 bits
            float* Af = (float*)(smem + SC_OFF_A);
            uint32_t* Au = (uint32_t*)(smem + SC_OFF_A);
            for (int i = tid; i < 4 * 4608; i += 256) Au[i] = f2tf(Af[i]);
        }
        // preconvert this p's B (4 chunks) into fragment-ordered tf32
        {
            const float* Braw = (const float*)(smem + SC_OFF_B + p * 18432);
#pragma unroll
            for (int q = 0; q < 2; ++q) {
                int f = tid + q * 256;            // 0..511 (within-chunk frag id)
                int ks = f >> 7;
                int rem = f & 127;
                int nt = rem >> 5, r4p = (rem >> 2) & 7, ccp = f & 3;
                int n = nt * 8 + r4p;
#pragma unroll
                for (int chunk = 0; chunk < 4; ++chunk) {
                    const float* src = Braw + chunk * 1152 + n * 36 + ks * 8 + ccp;
                    uint2 w;
                    w.x = f2tf(src[0]);
                    w.y = f2tf(src[4]);
                    BcU[chunk * 512 + f] = w;
                }
            }
        }
        __syncthreads();   // converted A + Bc ready

        float acc[4][4];
#pragma unroll
        for (int i = 0; i < 4; ++i)
#pragma unroll
            for (int j = 0; j < 4; ++j) acc[i][j] = 0.0f;

#pragma unroll
        for (int chunk = 0; chunk < 4; ++chunk) {
            const uint32_t* Au = (const uint32_t*)(smem + SC_OFF_A + chunk * 18432);
            const uint2* Bc = BcU + chunk * 512;
#pragma unroll
            for (int ks = 0; ks < 4; ++ks) {
                int k0 = ks * 8;
                uint32_t a0 = Au[row0 * 36 + k0 + cc];
                uint32_t a1 = Au[(row0 + 8) * 36 + k0 + cc];
                uint32_t a2 = Au[row0 * 36 + k0 + cc + 4];
                uint32_t a3 = Au[(row0 + 8) * 36 + k0 + cc + 4];
#pragma unroll
                for (int nt = 0; nt < 4; ++nt) {
                    uint2 bv2 = Bc[ks * 128 + nt * 32 + (r4 << 2) + cc];
                    mma_tf32(acc[nt], a0, a1, a2, a3, bv2.x, bv2.y);
                }
            }
        }
        // epilogue: tanh + bw weight; per-warp partial into per-p red
#pragma unroll
        for (int nt = 0; nt < 4; ++nt) {
            int col0 = nt * 8 + c2;
            float cs0 = ftanh(acc[nt][0] + fbs_t[row0 * 33 + col0]) * bw0
                      + ftanh(acc[nt][2] + fbs_t[(row0 + 8) * 33 + col0]) * bw1;
            float cs1 = ftanh(acc[nt][1] + fbs_t[row0 * 33 + col0 + 1]) * bw0
                      + ftanh(acc[nt][3] + fbs_t[(row0 + 8) * 33 + col0 + 1]) * bw1;
#pragma unroll
            for (int o = 4; o < 32; o <<= 1) {
                cs0 += __shfl_xor_sync(0xffffffffu, cs0, o);
                cs1 += __shfl_xor_sync(0xffffffffu, cs1, o);
            }
            if (r4 == 0) {
                red[p * 256 + wid * 32 + col0] = cs0;
                red[p * 256 + wid * 32 + col0 + 1] = cs1;
            }
        }
        __syncthreads();   // Bc reuse next iter: all warps done reading
    }
    if (tid < 128) {
        int p = tid >> 5, bb = tid & 31;
        float s = 0.0f;
#pragma unroll
        for (int w = 0; w < 8; ++w) s += red[p * 256 + w * 32 + bb];
        g_scores[bb * P + p0 + p] = s;   // beta_b omitted: softmax shift-invariant
    }
}

// ---------------- Kernel 2: softmax + logp ----------------
__global__ __launch_bounds__(256, 1) void k_softmax(float* __restrict__ out) {
    __shared__ float sm[256];
    int b = blockIdx.x;
    int tid = threadIdx.x;
    float s0 = g_scores[b * P + tid];
    float s1 = g_scores[b * P + tid + 256];
    sm[tid] = fmaxf(s0, s1);
    __syncthreads();
    for (int o = 128; o > 0; o >>= 1) {
        if (tid < o) sm[tid] = fmaxf(sm[tid], sm[tid + o]);
        __syncthreads();
    }
    float mx = sm[0];
    __syncthreads();
    float e0 = __expf(s0 - mx), e1 = __expf(s1 - mx);
    sm[tid] = e0 + e1;
    __syncthreads();
    for (int o = 128; o > 0; o >>= 1) {
        if (tid < o) sm[tid] += sm[tid + o];
        __syncthreads();
    }
    float Z = sm[0];
    float lz = __logf(Z);
    float inv = 1.0f / Z;
    g_beta[b * P + tid] = e0 * inv;
    g_beta[b * P + tid + 256] = e1 * inv;
    out[2 * B * H + b * P + tid] = s0 - mx - lz;
    out[2 * B * H + b * P + tid + 256] = s1 - mx - lz;
}

// ---------------- Kernel 3: tf32 mma split-K GEMM (unchanged from R11) ----------------
__global__ __launch_bounds__(128, 3) void k_gemm_tc(const float* __restrict__ Wih,
                                                    const float* __restrict__ Hr) {
    extern __shared__ char smem[];
    int tid = threadIdx.x, wid = tid >> 5, lane = tid & 31;
    int jb = blockIdx.x * 128;
    int cch = blockIdx.y;
    int c0 = (cch * CHUNKS) / NCHUNK, c1 = ((cch + 1) * CHUNKS) / NCHUNK;
    int total = c1 - c0;   // 18 or 19
    int p0 = c0 >> 2;

    const float* aptr[8];
    uint32_t adst[8];
#pragma unroll
    for (int r = 0; r < 8; ++r) {
        int seg = tid + 128 * r;
        int row = seg >> 3, c16 = seg & 7;
        aptr[r] = Wih + (size_t)(jb + row) * KBIG + c16 * 4;
        adst[r] = row * 144 + c16 * 16;
    }
    int bb0 = tid >> 3, bb1 = bb0 + 16;
    int bcol = (tid & 7) * 4;
    const float* bptr0 = Hr + bb0 * H + bcol;
    const float* bptr1 = Hr + bb1 * H + bcol;
    uint32_t bdst0 = bb0 * 144 + (tid & 7) * 16;
    uint32_t bdst1 = bb1 * 144 + (tid & 7) * 16;
    uint32_t sb = smem_addr(smem);

    auto issue = [&](int chunk, int st) {
#pragma unroll
        for (int r = 0; r < 8; ++r)
            cpa16(sb + OFF_A + st * A_STAGE + adst[r], aptr[r] + chunk * 32);
        int pp = chunk >> 2, h0 = (chunk & 3) * 32;
        cpa16(sb + OFF_B + st * B_STAGE + bdst0, bptr0 + pp * (B * H) + h0);
        cpa16(sb + OFF_B + st * B_STAGE + bdst1, bptr1 + pp * (B * H) + h0);
        asm volatile("cp.async.commit_group;");
    };

    issue(c0 + 0, 0);
    issue(c0 + 1, 1);

    float* bsl = (float*)(smem + OFF_BETA);
    {
        int np = ((c1 - 1) >> 2) - p0 + 1;
        for (int t = tid; t < 32 * 17; t += 128) {
            int b = t / 17, pi = t - b * 17;
            if (pi < np) bsl[t] = g_beta[b * P + p0 + pi];
        }
    }
    uint2* BcU = (uint2*)(smem + OFF_BC);

    float acc[2][4][4];
#pragma unroll
    for (int m = 0; m < 2; ++m)
#pragma unroll
        for (int i = 0; i < 4; ++i)
#pragma unroll
            for (int j = 0; j < 4; ++j) acc[m][i][j] = 0.0f;

    int pc_ks[4], pc_n[4], pc_cc[4];
#pragma unroll
    for (int q = 0; q < 4; ++q) {
        int f = tid + q * 128;
        pc_ks[q] = f >> 7;
        int rem = f & 127;
        pc_n[q] = (rem >> 5) * 8 + ((rem >> 2) & 7);
        pc_cc[q] = f & 3;
    }

    int r4 = lane >> 2, cc = lane & 3;
    int rowb = wid * 32 + r4;
    for (int i = 0; i < total; ++i) {
        int st = i % STAGES;
        if (i == total - 1) asm volatile("cp.async.wait_group 0;");
        else                asm volatile("cp.async.wait_group 1;");
        __syncthreads();
        if (i + 2 < total) issue(c0 + i + 2, (i + 2) % STAGES);

        {
            int pi = ((c0 + i) >> 2) - p0;
            const float* Braw = (const float*)(smem + OFF_B + st * B_STAGE);
#pragma unroll
            for (int q = 0; q < 4; ++q) {
                float bv = bsl[pc_n[q] * 17 + pi];
                const float* src = Braw + pc_n[q] * 36 + pc_ks[q] * 8 + pc_cc[q];
                uint2 w;
                w.x = f2tf(src[0] * bv);
                w.y = f2tf(src[4] * bv);
                BcU[tid + q * 128] = w;
            }
        }
        __syncthreads();

        const float* As = (const float*)(smem + OFF_A + st * A_STAGE);
#pragma unroll
        for (int ks = 0; ks < 4; ++ks) {
            int k0 = ks * 8;
            uint32_t a00 = f2tf(As[rowb * 36 + k0 + cc]);
            uint32_t a01 = f2tf(As[(rowb + 8) * 36 + k0 + cc]);
            uint32_t a02 = f2tf(As[rowb * 36 + k0 + cc + 4]);
            uint32_t a03 = f2tf(As[(rowb + 8) * 36 + k0 + cc + 4]);
            uint32_t a10 = f2tf(As[(rowb + 16) * 36 + k0 + cc]);
            uint32_t a11 = f2tf(As[(rowb + 24) * 36 + k0 + cc]);
            uint32_t a12 = f2tf(As[(rowb + 16) * 36 + k0 + cc + 4]);
            uint32_t a13 = f2tf(As[(rowb + 24) * 36 + k0 + cc + 4]);
#pragma unroll
            for (int nt = 0; nt < 4; ++nt) {
                uint2 bv2 = BcU[ks * 128 + nt * 32 + (r4 << 2) + cc];
                mma_tf32(acc[0][nt], a00, a01, a02, a03, bv2.x, bv2.y);
                mma_tf32(acc[1][nt], a10, a11, a12, a13, bv2.x, bv2.y);
            }
        }
    }

    int c2 = (lane & 3) * 2;
#pragma unroll
    for (int m = 0; m < 2; ++m) {
#pragma unroll
        for (int nt = 0; nt < 4; ++nt) {
            int col = nt * 8 + c2;
            int row0 = jb + wid * 32 + m * 16 + r4;
            *(float2*)&g_gpart[(cch * K4H + row0) * B + col] =
                make_float2(acc[m][nt][0], acc[m][nt][1]);
            *(float2*)&g_gpart[(cch * K4H + row0 + 8) * B + col] =
                make_float2(acc[m][nt][2], acc[m][nt][3]);
        }
    }
}

// ---------------- Kernel 4: fused gates0 + split-K reduce + LSTM ----------------
// One block per h. c-loop unrolled x4 -> 16 independent LDGs in flight per warp
// (MLP 4 -> 16) to cover DRAM latency; was 513 GB/s at MLP 4.
__global__ __launch_bounds__(256, 1) void k_fin(const float* __restrict__ hidden,
                                                const float* __restrict__ hak,
                                                const float* __restrict__ Whh,
                                                const float* __restrict__ bih,
                                                const float* __restrict__ bhh,
                                                float* __restrict__ out) {
    __shared__ float hak_s[B * 129];     // stride 129: conflict-free lane-b LDS
    __shared__ float red[8][4][32];
    __shared__ float red2[4][2][32];
    int tid = threadIdx.x;
    int b = tid & 31;
    int q = tid >> 5;                    // 0..7
    int h = blockIdx.x;                  // 0..127

    // stage hak (coalesced read, strided store)
    for (int i = tid; i < B * H; i += 256) {
        hak_s[(i >> 7) * 129 + (i & 127)] = hak[i];
    }
    __syncthreads();

    // gates0 partial: warp q -> (gi = q>>1, half = q&1), lanes over b
    {
        int gi = q >> 1, half = q & 1;
        int j = gi * H + h;
        const float4* wr = (const float4*)(Whh + j * H) + half * 16;
        float acc = 0.0f;
#pragma unroll
        for (int kk = 0; kk < 16; ++kk) {
            float4 w4 = __ldg(wr + kk);          // broadcast across lanes
            int k = half * 64 + kk * 4;
            const float* hs = &hak_s[b * 129 + k];
            acc += w4.x * hs[0] + w4.y * hs[1] + w4.z * hs[2] + w4.w * hs[3];
        }
        red2[gi][half][b] = acc;
    }

    // split-K partial reduction over g_gpart (slice q), c-loop unrolled x4:
    // 4 gi x 4 c = 16 independent 128B-line loads in flight per warp.
    {
        float acc[4] = {0.f, 0.f, 0.f, 0.f};
        int cbeg = q * 14;
        int cend = cbeg + 14 < NCHUNK ? cbeg + 14 : NCHUNK;
        int c = cbeg;
        for (; c + 4 <= cend; c += 4) {
            float v[4][4];
#pragma unroll
            for (int u = 0; u < 4; ++u)
#pragma unroll
                for (int gi = 0; gi < 4; ++gi)
                    v[u][gi] = g_gpart[((c + u) * K4H + gi * H + h) * B + b];
#pragma unroll
            for (int u = 0; u < 4; ++u)
#pragma unroll
                for (int gi = 0; gi < 4; ++gi)
                    acc[gi] += v[u][gi];
        }
        for (; c < cend; ++c) {
#pragma unroll
            for (int gi = 0; gi < 4; ++gi)
                acc[gi] += g_gpart[(c * K4H + gi * H + h) * B + b];
        }
#pragma unroll
        for (int gi = 0; gi < 4; ++gi) red[q][gi][b] = acc[gi];
    }
    __syncthreads();

    if (tid < 32) {
        float sg[4];
#pragma unroll
        for (int gi = 0; gi < 4; ++gi) {
            int j = gi * H + h;
            float v = __ldg(bih + j) + __ldg(bhh + j)
                    + red2[gi][0][b] + red2[gi][1][b];
#pragma unroll
            for (int w = 0; w < 8; ++w) v += red[w][gi][b];
            sg[gi] = v;
        }
        float cv = fsigmoid(sg[1]) * hidden[b * H + h] + fsigmoid(sg[0]) * ftanh(sg[2]);
        float hn = fsigmoid(sg[3]) * ftanh(cv);
        out[b * H + h] = hn;
        out[B * H + b * H + h] = cv;
    }
}

// ---------------- launch ----------------
extern "C" void kernel_launch(void* const* d_in, const int* in_sizes, int n_in,
                              void* d_out, int out_size) {
    const float* hak    = (const float*)d_in[0];
    const float* Hr     = (const float*)d_in[1];
    const float* hidden = (const float*)d_in[2];
    const float* Wf     = (const float*)d_in[3];
    const float* bf     = (const float*)d_in[4];
    const float* Wfn    = (const float*)d_in[5];
    const float* bw     = (const float*)d_in[6];
    // d_in[7] = beta_b (scalar): softmax/log_softmax shift-invariant -> unused
    const float* Wih    = (const float*)d_in[8];
    const float* Whh    = (const float*)d_in[9];
    const float* bih    = (const float*)d_in[10];
    const float* bhh    = (const float*)d_in[11];
    float* out = (float*)d_out;

    static int smem_set = 0;
    if (!smem_set) {
        cudaFuncSetAttribute(k_gemm_tc, cudaFuncAttributeMaxDynamicSharedMemorySize, GEMM_SMEM);
        cudaFuncSetAttribute(k_scores_tc, cudaFuncAttributeMaxDynamicSharedMemorySize, SC_SMEM);
        smem_set = 1;
    }

    k_scores_tc<<<P / 4, 256, SC_SMEM>>>(Hr, Wfn, Wf, hak, bf, bw);
    k_softmax<<<B, 256>>>(out);
    k_gemm_tc<<<dim3(4, NCHUNK), 128, GEMM_SMEM>>>(Wih, Hr);
    k_fin<<<H, 256>>>(hidden, hak, Whh, bih, bhh, out);
}

// round 16
// speedup vs baseline: 2.7299x; 1.0676x over previous
#include <cuda_runtime.h>
#include <cstdint>
#include <math.h>

// Problem constants
#define H 128
#define P 512
#define B 32
#define K4H 512          // 4*H
#define KBIG 65536       // P*H
#define NCHUNK 111       // 4 j-tiles * 111 = 444 CTAs = 3 CTA/SM, one wave
#define CHUNKS 2048      // KBIG / 32 (k-chunks of 32 floats)
#define STAGES 3

// k_gemm_tc smem layout (A rows padded to 36 floats: conflict-free frag LDS)
#define A_STAGE 18432               // 128 rows * 36 floats * 4B
#define B_STAGE 4608                // 32 rows * 36 floats * 4B
#define OFF_BETA 0                  // 32*17 floats = 2176 B
#define OFF_BC   2304               // 512 uint2 = 4096 B (tf32+beta B tile, frag order)
#define OFF_A    6400
#define OFF_B    (OFF_A + STAGES * A_STAGE)          // 61696
#define GEMM_SMEM (OFF_B + STAGES * B_STAGE)         // 75520 (x3 CTA = 226.6KB/SM)

// k_scores_tc smem layout
#define SC_OFF_A   0                                 // 4 chunks * 18432 = 73728
#define SC_OFF_B   73728                             // 4 p * 18432 = 73728
#define SC_OFF_FB  147456                            // fbs_t[128][33] = 16896
#define SC_OFF_RED 164352                            // 4 p * 8 warps * 32 * 4B = 4096
#define SC_OFF_BC  168448                            // 4 chunks * 512 uint2 = 16384
#define SC_SMEM    184832

// ---------------- scratch (device globals; device-code use ONLY) ----------------
__device__ float g_scores[B * P];
__device__ float g_beta[B * P];
__device__ float g_gpart[NCHUNK * K4H * B];          // 7.27 MB

// ---------------- helpers ----------------
__device__ __forceinline__ float fsigmoid(float x) { return 1.0f / (1.0f + __expf(-x)); }
__device__ __forceinline__ float ftanh(float x) {
    float ax = fabsf(x);
    float e  = __expf(2.0f * ax);
    float t  = 1.0f - 2.0f / (e + 1.0f);
    return copysignf(t, x);
}
__device__ __forceinline__ uint32_t f2tf(float x) {
    uint32_t r;
    asm("cvt.rna.tf32.f32 %0, %1;" : "=r"(r) : "f"(x));
    return r;
}
__device__ __forceinline__ void mma_tf32(float* c, uint32_t a0, uint32_t a1,
                                         uint32_t a2, uint32_t a3,
                                         uint32_t b0, uint32_t b1) {
    asm volatile(
        "mma.sync.aligned.m16n8k8.row.col.f32.tf32.tf32.f32 "
        "{%0,%1,%2,%3}, {%4,%5,%6,%7}, {%8,%9}, {%0,%1,%2,%3};"
        : "+f"(c[0]), "+f"(c[1]), "+f"(c[2]), "+f"(c[3])
        : "r"(a0), "r"(a1), "r"(a2), "r"(a3), "r"(b0), "r"(b1));
}
__device__ __forceinline__ uint32_t smem_addr(const void* p) {
    uint32_t a;
    asm("{ .reg .u64 t; cvta.to.shared.u64 t, %1; cvt.u32.u64 %0, t; }" : "=r"(a) : "l"(p));
    return a;
}
__device__ __forceinline__ void cpa16(uint32_t dst, const void* src) {
    asm volatile("cp.async.cg.shared.global [%0], [%1], 16;" :: "r"(dst), "l"(src));
}

// ---------------- Kernel 1: tf32 mma scores + in-block fb ----------------
// Per block: 4 consecutive p. fb = hak @ Wf^T + bf computed first via MMA
// (A slot holds Wf, B0 holds hak), then slots reloaded with Wfn / Hr[p0].
// Process order p1,p2,p3,p0 so fb compute overlaps Hr prefetch.
__global__ __launch_bounds__(256, 1) void k_scores_tc(const float* __restrict__ Hr,
                                                      const float* __restrict__ Wfn,
                                                      const float* __restrict__ Wf,
                                                      const float* __restrict__ hak,
                                                      const float* __restrict__ bf,
                                                      const float* __restrict__ bw) {
    extern __shared__ char smem[];
    int tid = threadIdx.x, wid = tid >> 5, lane = tid & 31;
    int p0 = blockIdx.x * 4;
    uint32_t sb = smem_addr(smem);

    int r4 = lane >> 2, cc = lane & 3, c2 = cc * 2;
    int row0 = wid * 16 + r4;

    // G0: Wf -> A slot (4096 cells), hak -> B0 (1024 cells)
#pragma unroll
    for (int r = 0; r < 16; ++r) {
        int idx = tid + 256 * r;
        int chunk = idx >> 10, rem = idx & 1023;
        int row = rem >> 3, c16 = rem & 7;
        cpa16(sb + SC_OFF_A + chunk * 18432 + row * 144 + c16 * 16,
              Wf + row * H + chunk * 32 + c16 * 4);
    }
#pragma unroll
    for (int r = 0; r < 4; ++r) {
        int idx = tid + 256 * r;
        int chunk = idx >> 8, rem = idx & 255;
        int row = rem >> 3, c16 = rem & 7;
        cpa16(sb + SC_OFF_B + chunk * 4608 + row * 144 + c16 * 16,
              hak + row * H + chunk * 32 + c16 * 4);
    }
    asm volatile("cp.async.commit_group;");   // G0
    // G1..G3: Hr[p1..p3] -> B1..B3
#pragma unroll
    for (int p = 1; p < 4; ++p) {
#pragma unroll
        for (int r = 0; r < 4; ++r) {
            int idx = tid + 256 * r;
            int chunk = idx >> 8, rem = idx & 255;
            int row = rem >> 3, c16 = rem & 7;
            cpa16(sb + SC_OFF_B + p * 18432 + chunk * 4608 + row * 144 + c16 * 16,
                  Hr + (p0 + p) * (B * H) + row * H + chunk * 32 + c16 * 4);
        }
        asm volatile("cp.async.commit_group;");
    }

    float* fbs_t = (float*)(smem + SC_OFF_FB);
    float* red = (float*)(smem + SC_OFF_RED);
    uint2* BcU = (uint2*)(smem + SC_OFF_BC);

    float bw0 = __ldg(bw + row0), bw1 = __ldg(bw + row0 + 8);
    float bf0 = __ldg(bf + row0), bf8 = __ldg(bf + row0 + 8);

    // ---- fb phase: wait G0, compute fb = Wf @ hak^T via on-the-fly tf32 MMA ----
    asm volatile("cp.async.wait_group 3;");   // G0 done (G1..G3 may pend)
    __syncthreads();
    {
        float accf[4][4];
#pragma unroll
        for (int i = 0; i < 4; ++i)
#pragma unroll
            for (int j = 0; j < 4; ++j) accf[i][j] = 0.0f;
#pragma unroll
        for (int chunk = 0; chunk < 4; ++chunk) {
            const float* As = (const float*)(smem + SC_OFF_A + chunk * 18432);
            const float* Bs = (const float*)(smem + SC_OFF_B + chunk * 4608);
#pragma unroll
            for (int ks = 0; ks < 4; ++ks) {
                int k0 = ks * 8;
                uint32_t a0 = f2tf(As[row0 * 36 + k0 + cc]);
                uint32_t a1 = f2tf(As[(row0 + 8) * 36 + k0 + cc]);
                uint32_t a2 = f2tf(As[row0 * 36 + k0 + cc + 4]);
                uint32_t a3 = f2tf(As[(row0 + 8) * 36 + k0 + cc + 4]);
#pragma unroll
                for (int nt = 0; nt < 4; ++nt) {
                    uint32_t b0 = f2tf(Bs[(nt * 8 + r4) * 36 + k0 + cc]);
                    uint32_t b1 = f2tf(Bs[(nt * 8 + r4) * 36 + k0 + cc + 4]);
                    mma_tf32(accf[nt], a0, a1, a2, a3, b0, b1);
                }
            }
        }
        // fbs_t[h*33 + b] = fb[b][h] = acc + bf[h]
#pragma unroll
        for (int nt = 0; nt < 4; ++nt) {
            int col = nt * 8 + c2;
            fbs_t[row0 * 33 + col]           = accf[nt][0] + bf0;
            fbs_t[row0 * 33 + col + 1]       = accf[nt][1] + bf0;
            fbs_t[(row0 + 8) * 33 + col]     = accf[nt][2] + bf8;
            fbs_t[(row0 + 8) * 33 + col + 1] = accf[nt][3] + bf8;
        }
    }
    __syncthreads();   // all reads of A(Wf)/B0(hak) done -> safe to overwrite

    // G4: Wfn -> A ; G5: Hr[p0] -> B0
#pragma unroll
    for (int r = 0; r < 16; ++r) {
        int idx = tid + 256 * r;
        int chunk = idx >> 10, rem = idx & 1023;
        int row = rem >> 3, c16 = rem & 7;
        cpa16(sb + SC_OFF_A + chunk * 18432 + row * 144 + c16 * 16,
              Wfn + row * H + chunk * 32 + c16 * 4);
    }
    asm volatile("cp.async.commit_group;");   // G4
#pragma unroll
    for (int r = 0; r < 4; ++r) {
        int idx = tid + 256 * r;
        int chunk = idx >> 8, rem = idx & 255;
        int row = rem >> 3, c16 = rem & 7;
        cpa16(sb + SC_OFF_B + chunk * 4608 + row * 144 + c16 * 16,
              Hr + p0 * (B * H) + row * H + chunk * 32 + c16 * 4);
    }
    asm volatile("cp.async.commit_group;");   // G5

    // ---- main p loop, order {1,2,3,0} ----
#pragma unroll
    for (int it = 0; it < 4; ++it) {
        int p = (it + 1) & 3;   // 1,2,3,0
        if (it < 3) asm volatile("cp.async.wait_group 1;");   // G0..G4 done
        else        asm volatile("cp.async.wait_group 0;");   // all done (B0=Hr[p0])
        __syncthreads();

        if (it == 0) {
            // one-time in-place A (Wfn) conversion to tf32 bits
            float* Af = (float*)(smem + SC_OFF_A);
            uint32_t* Au = (uint32_t*)(smem + SC_OFF_A);
            for (int i = tid; i < 4 * 4608; i += 256) Au[i] = f2tf(Af[i]);
        }
        // preconvert this p's B (4 chunks) into fragment-ordered tf32
        {
            const float* Braw = (const float*)(smem + SC_OFF_B + p * 18432);
#pragma unroll
            for (int q = 0; q < 2; ++q) {
                int f = tid + q * 256;            // 0..511 (within-chunk frag id)
                int ks = f >> 7;
                int rem = f & 127;
                int nt = rem >> 5, r4p = (rem >> 2) & 7, ccp = f & 3;
                int n = nt * 8 + r4p;
#pragma unroll
                for (int chunk = 0; chunk < 4; ++chunk) {
                    const float* src = Braw + chunk * 1152 + n * 36 + ks * 8 + ccp;
                    uint2 w;
                    w.x = f2tf(src[0]);
                    w.y = f2tf(src[4]);
                    BcU[chunk * 512 + f] = w;
                }
            }
        }
        __syncthreads();   // converted A + Bc ready

        float acc[4][4];
#pragma unroll
        for (int i = 0; i < 4; ++i)
#pragma unroll
            for (int j = 0; j < 4; ++j) acc[i][j] = 0.0f;

#pragma unroll
        for (int chunk = 0; chunk < 4; ++chunk) {
            const uint32_t* Au = (const uint32_t*)(smem + SC_OFF_A + chunk * 18432);
            const uint2* Bc = BcU + chunk * 512;
#pragma unroll
            for (int ks = 0; ks < 4; ++ks) {
                int k0 = ks * 8;
                uint32_t a0 = Au[row0 * 36 + k0 + cc];
                uint32_t a1 = Au[(row0 + 8) * 36 + k0 + cc];
                uint32_t a2 = Au[row0 * 36 + k0 + cc + 4];
                uint32_t a3 = Au[(row0 + 8) * 36 + k0 + cc + 4];
#pragma unroll
                for (int nt = 0; nt < 4; ++nt) {
                    uint2 bv2 = Bc[ks * 128 + nt * 32 + (r4 << 2) + cc];
                    mma_tf32(acc[nt], a0, a1, a2, a3, bv2.x, bv2.y);
                }
            }
        }
        // epilogue: tanh + bw weight; per-warp partial into per-p red
#pragma unroll
        for (int nt = 0; nt < 4; ++nt) {
            int col0 = nt * 8 + c2;
            float cs0 = ftanh(acc[nt][0] + fbs_t[row0 * 33 + col0]) * bw0
                      + ftanh(acc[nt][2] + fbs_t[(row0 + 8) * 33 + col0]) * bw1;
            float cs1 = ftanh(acc[nt][1] + fbs_t[row0 * 33 + col0 + 1]) * bw0
                      + ftanh(acc[nt][3] + fbs_t[(row0 + 8) * 33 + col0 + 1]) * bw1;
#pragma unroll
            for (int o = 4; o < 32; o <<= 1) {
                cs0 += __shfl_xor_sync(0xffffffffu, cs0, o);
                cs1 += __shfl_xor_sync(0xffffffffu, cs1, o);
            }
            if (r4 == 0) {
                red[p * 256 + wid * 32 + col0] = cs0;
                red[p * 256 + wid * 32 + col0 + 1] = cs1;
            }
        }
        __syncthreads();   // Bc reuse next iter: all warps done reading
    }
    if (tid < 128) {
        int p = tid >> 5, bb = tid & 31;
        float s = 0.0f;
#pragma unroll
        for (int w = 0; w < 8; ++w) s += red[p * 256 + w * 32 + bb];
        g_scores[bb * P + p0 + p] = s;   // beta_b omitted: softmax shift-invariant
    }
}

// ---------------- Kernel 2: softmax + logp ----------------
__global__ __launch_bounds__(256, 1) void k_softmax(float* __restrict__ out) {
    __shared__ float sm[256];
    int b = blockIdx.x;
    int tid = threadIdx.x;
    float s0 = g_scores[b * P + tid];
    float s1 = g_scores[b * P + tid + 256];
    sm[tid] = fmaxf(s0, s1);
    __syncthreads();
    for (int o = 128; o > 0; o >>= 1) {
        if (tid < o) sm[tid] = fmaxf(sm[tid], sm[tid + o]);
        __syncthreads();
    }
    float mx = sm[0];
    __syncthreads();
    float e0 = __expf(s0 - mx), e1 = __expf(s1 - mx);
    sm[tid] = e0 + e1;
    __syncthreads();
    for (int o = 128; o > 0; o >>= 1) {
        if (tid < o) sm[tid] += sm[tid + o];
        __syncthreads();
    }
    float Z = sm[0];
    float lz = __logf(Z);
    float inv = 1.0f / Z;
    g_beta[b * P + tid] = e0 * inv;
    g_beta[b * P + tid + 256] = e1 * inv;
    out[2 * B * H + b * P + tid] = s0 - mx - lz;
    out[2 * B * H + b * P + tid + 256] = s1 - mx - lz;
}

// ---------------- Kernel 3: tf32 mma split-K GEMM (unchanged from R11) ----------------
__global__ __launch_bounds__(128, 3) void k_gemm_tc(const float* __restrict__ Wih,
                                                    const float* __restrict__ Hr) {
    extern __shared__ char smem[];
    int tid = threadIdx.x, wid = tid >> 5, lane = tid & 31;
    int jb = blockIdx.x * 128;
    int cch = blockIdx.y;
    int c0 = (cch * CHUNKS) / NCHUNK, c1 = ((cch + 1) * CHUNKS) / NCHUNK;
    int total = c1 - c0;   // 18 or 19
    int p0 = c0 >> 2;

    const float* aptr[8];
    uint32_t adst[8];
#pragma unroll
    for (int r = 0; r < 8; ++r) {
        int seg = tid + 128 * r;
        int row = seg >> 3, c16 = seg & 7;
        aptr[r] = Wih + (size_t)(jb + row) * KBIG + c16 * 4;
        adst[r] = row * 144 + c16 * 16;
    }
    int bb0 = tid >> 3, bb1 = bb0 + 16;
    int bcol = (tid & 7) * 4;
    const float* bptr0 = Hr + bb0 * H + bcol;
    const float* bptr1 = Hr + bb1 * H + bcol;
    uint32_t bdst0 = bb0 * 144 + (tid & 7) * 16;
    uint32_t bdst1 = bb1 * 144 + (tid & 7) * 16;
    uint32_t sb = smem_addr(smem);

    auto issue = [&](int chunk, int st) {
#pragma unroll
        for (int r = 0; r < 8; ++r)
            cpa16(sb + OFF_A + st * A_STAGE + adst[r], aptr[r] + chunk * 32);
        int pp = chunk >> 2, h0 = (chunk & 3) * 32;
        cpa16(sb + OFF_B + st * B_STAGE + bdst0, bptr0 + pp * (B * H) + h0);
        cpa16(sb + OFF_B + st * B_STAGE + bdst1, bptr1 + pp * (B * H) + h0);
        asm volatile("cp.async.commit_group;");
    };

    issue(c0 + 0, 0);
    issue(c0 + 1, 1);

    float* bsl = (float*)(smem + OFF_BETA);
    {
        int np = ((c1 - 1) >> 2) - p0 + 1;
        for (int t = tid; t < 32 * 17; t += 128) {
            int b = t / 17, pi = t - b * 17;
            if (pi < np) bsl[t] = g_beta[b * P + p0 + pi];
        }
    }
    uint2* BcU = (uint2*)(smem + OFF_BC);

    float acc[2][4][4];
#pragma unroll
    for (int m = 0; m < 2; ++m)
#pragma unroll
        for (int i = 0; i < 4; ++i)
#pragma unroll
            for (int j = 0; j < 4; ++j) acc[m][i][j] = 0.0f;

    int pc_ks[4], pc_n[4], pc_cc[4];
#pragma unroll
    for (int q = 0; q < 4; ++q) {
        int f = tid + q * 128;
        pc_ks[q] = f >> 7;
        int rem = f & 127;
        pc_n[q] = (rem >> 5) * 8 + ((rem >> 2) & 7);
        pc_cc[q] = f & 3;
    }

    int r4 = lane >> 2, cc = lane & 3;
    int rowb = wid * 32 + r4;
    for (int i = 0; i < total; ++i) {
        int st = i % STAGES;
        if (i == total - 1) asm volatile("cp.async.wait_group 0;");
        else                asm volatile("cp.async.wait_group 1;");
        __syncthreads();
        if (i + 2 < total) issue(c0 + i + 2, (i + 2) % STAGES);

        {
            int pi = ((c0 + i) >> 2) - p0;
            const float* Braw = (const float*)(smem + OFF_B + st * B_STAGE);
#pragma unroll
            for (int q = 0; q < 4; ++q) {
                float bv = bsl[pc_n[q] * 17 + pi];
                const float* src = Braw + pc_n[q] * 36 + pc_ks[q] * 8 + pc_cc[q];
                uint2 w;
                w.x = f2tf(src[0] * bv);
                w.y = f2tf(src[4] * bv);
                BcU[tid + q * 128] = w;
            }
        }
        __syncthreads();

        const float* As = (const float*)(smem + OFF_A + st * A_STAGE);
#pragma unroll
        for (int ks = 0; ks < 4; ++ks) {
            int k0 = ks * 8;
            uint32_t a00 = f2tf(As[rowb * 36 + k0 + cc]);
            uint32_t a01 = f2tf(As[(rowb + 8) * 36 + k0 + cc]);
            uint32_t a02 = f2tf(As[rowb * 36 + k0 + cc + 4]);
            uint32_t a03 = f2tf(As[(rowb + 8) * 36 + k0 + cc + 4]);
            uint32_t a10 = f2tf(As[(rowb + 16) * 36 + k0 + cc]);
            uint32_t a11 = f2tf(As[(rowb + 24) * 36 + k0 + cc]);
            uint32_t a12 = f2tf(As[(rowb + 16) * 36 + k0 + cc + 4]);
            uint32_t a13 = f2tf(As[(rowb + 24) * 36 + k0 + cc + 4]);
#pragma unroll
            for (int nt = 0; nt < 4; ++nt) {
                uint2 bv2 = BcU[ks * 128 + nt * 32 + (r4 << 2) + cc];
                mma_tf32(acc[0][nt], a00, a01, a02, a03, bv2.x, bv2.y);
                mma_tf32(acc[1][nt], a10, a11, a12, a13, bv2.x, bv2.y);
            }
        }
    }

    int c2 = (lane & 3) * 2;
#pragma unroll
    for (int m = 0; m < 2; ++m) {
#pragma unroll
        for (int nt = 0; nt < 4; ++nt) {
            int col = nt * 8 + c2;
            int row0 = jb + wid * 32 + m * 16 + r4;
            *(float2*)&g_gpart[(cch * K4H + row0) * B + col] =
                make_float2(acc[m][nt][0], acc[m][nt][1]);
            *(float2*)&g_gpart[(cch * K4H + row0 + 8) * B + col] =
                make_float2(acc[m][nt][2], acc[m][nt][3]);
        }
    }
}

// ---------------- Kernel 4: fused gates0 + split-K reduce + LSTM ----------------
// 1024 threads/block (32 warps): 4x the in-flight loads vs 256-thread version
// (measured per-warp effective MLP ~2 regardless of unroll -> scale warp count).
// Warp q handles chunk slice [q*4, q*4+4); warps 0..7 also compute gates0.
__global__ __launch_bounds__(1024, 1) void k_fin(const float* __restrict__ hidden,
                                                 const float* __restrict__ hak,
                                                 const float* __restrict__ Whh,
                                                 const float* __restrict__ bih,
                                                 const float* __restrict__ bhh,
                                                 float* __restrict__ out) {
    __shared__ float hak_s[B * 129];     // stride 129: conflict-free lane-b LDS
    __shared__ float red[32][4][32];     // 16 KB: [slice][gi][b]
    __shared__ float red2[4][2][32];
    int tid = threadIdx.x;
    int b = tid & 31;
    int q = tid >> 5;                    // warp/slice 0..31
    int h = blockIdx.x;                  // 0..127

    // stage hak (coalesced read, strided store)
    for (int i = tid; i < B * H; i += 1024) {
        hak_s[(i >> 7) * 129 + (i & 127)] = hak[i];
    }
    __syncthreads();

    // gates0 partial on warps 0..7: warp q -> (gi = q>>1, half = q&1)
    if (q < 8) {
        int gi = q >> 1, half = q & 1;
        int j = gi * H + h;
        const float4* wr = (const float4*)(Whh + j * H) + half * 16;
        float acc = 0.0f;
#pragma unroll
        for (int kk = 0; kk < 16; ++kk) {
            float4 w4 = __ldg(wr + kk);          // broadcast across lanes
            int k = half * 64 + kk * 4;
            const float* hs = &hak_s[b * 129 + k];
            acc += w4.x * hs[0] + w4.y * hs[1] + w4.z * hs[2] + w4.w * hs[3];
        }
        red2[gi][half][b] = acc;
    }

    // split-K partial reduction: slice q covers chunks [q*4, min(q*4+4, NCHUNK))
    {
        float acc[4] = {0.f, 0.f, 0.f, 0.f};
        int cbeg = q * 4;
#pragma unroll
        for (int u = 0; u < 4; ++u) {
            int c = cbeg + u;
            if (c < NCHUNK) {
#pragma unroll
                for (int gi = 0; gi < 4; ++gi)
                    acc[gi] += g_gpart[(c * K4H + gi * H + h) * B + b];
            }
        }
#pragma unroll
        for (int gi = 0; gi < 4; ++gi) red[q][gi][b] = acc[gi];
    }
    __syncthreads();

    if (tid < 32) {
        float sg[4];
#pragma unroll
        for (int gi = 0; gi < 4; ++gi) {
            int j = gi * H + h;
            float v = __ldg(bih + j) + __ldg(bhh + j)
                    + red2[gi][0][b] + red2[gi][1][b];
#pragma unroll
            for (int w = 0; w < 32; ++w) v += red[w][gi][b];
            sg[gi] = v;
        }
        float cv = fsigmoid(sg[1]) * hidden[b * H + h] + fsigmoid(sg[0]) * ftanh(sg[2]);
        float hn = fsigmoid(sg[3]) * ftanh(cv);
        out[b * H + h] = hn;
        out[B * H + b * H + h] = cv;
    }
}

// ---------------- launch ----------------
extern "C" void kernel_launch(void* const* d_in, const int* in_sizes, int n_in,
                              void* d_out, int out_size) {
    const float* hak    = (const float*)d_in[0];
    const float* Hr     = (const float*)d_in[1];
    const float* hidden = (const float*)d_in[2];
    const float* Wf     = (const float*)d_in[3];
    const float* bf     = (const float*)d_in[4];
    const float* Wfn    = (const float*)d_in[5];
    const float* bw     = (const float*)d_in[6];
    // d_in[7] = beta_b (scalar): softmax/log_softmax shift-invariant -> unused
    const float* Wih    = (const float*)d_in[8];
    const float* Whh    = (const float*)d_in[9];
    const float* bih    = (const float*)d_in[10];
    const float* bhh    = (const float*)d_in[11];
    float* out = (float*)d_out;

    static int smem_set = 0;
    if (!smem_set) {
        cudaFuncSetAttribute(k_gemm_tc, cudaFuncAttributeMaxDynamicSharedMemorySize, GEMM_SMEM);
        cudaFuncSetAttribute(k_scores_tc, cudaFuncAttributeMaxDynamicSharedMemorySize, SC_SMEM);
        smem_set = 1;
    }

    k_scores_tc<<<P / 4, 256, SC_SMEM>>>(Hr, Wfn, Wf, hak, bf, bw);
    k_softmax<<<B, 256>>>(out);
    k_gemm_tc<<<dim3(4, NCHUNK), 128, GEMM_SMEM>>>(Wih, Hr);
    k_fin<<<H, 1024>>>(hidden, hak, Whh, bih, bhh, out);
}